// round 6
// baseline (speedup 1.0000x reference)
#include <cuda_runtime.h>
#include <math.h>
#include <stdint.h>

#define NN   50000
#define EE   800000
#define E2V  (EE + NN)
#define F1   256
#define OUTC 40
#define SB   512
#define NBLK ((NN + SB - 1) / SB)

// ---- scratch ----
__device__ float g_h   [(size_t)NN * F1];
__device__ float g_out [(size_t)NN * F1];
__device__ float g_asrc[NN * 8];
__device__ float g_adst[NN * 8];
__device__ int   g_deg [NN];
__device__ int   g_rows[NN + 1];
__device__ int   g_cur [NN];
__device__ int   g_colsrc[E2V];
__device__ int   g_bsum[NBLK + 1];

// ===========================================================================
// CSR build (dst-grouped): count -> scan -> scatter
// ===========================================================================
__global__ void init_deg_k()
{
    int i = blockIdx.x * blockDim.x + threadIdx.x;
    if (i < NN) g_deg[i] = 1;
}

__global__ void count_k(const int* __restrict__ dst)
{
    int e = blockIdx.x * blockDim.x + threadIdx.x;
    if (e < EE) atomicAdd(&g_deg[dst[e]], 1);
}

__global__ void scan1_k()
{
    __shared__ int sh[SB];
    int i = blockIdx.x * SB + threadIdx.x;
    sh[threadIdx.x] = (i < NN) ? g_deg[i] : 0;
    __syncthreads();
    #pragma unroll
    for (int o = 1; o < SB; o <<= 1) {
        int t = (threadIdx.x >= o) ? sh[threadIdx.x - o] : 0;
        __syncthreads();
        sh[threadIdx.x] += t;
        __syncthreads();
    }
    if (i < NN) g_rows[i + 1] = sh[threadIdx.x];
    if (threadIdx.x == SB - 1) g_bsum[blockIdx.x] = sh[SB - 1];
}

__global__ void scan2_k()
{
    __shared__ int sh[128];
    int t = threadIdx.x;
    int v = (t < NBLK) ? g_bsum[t] : 0;
    sh[t] = v;
    __syncthreads();
    #pragma unroll
    for (int o = 1; o < 128; o <<= 1) {
        int u = (t >= o) ? sh[t - o] : 0;
        __syncthreads();
        sh[t] += u;
        __syncthreads();
    }
    if (t < NBLK) g_bsum[t] = sh[t] - v;   // exclusive
}

__global__ void scan3_k()
{
    int i = blockIdx.x * blockDim.x + threadIdx.x;
    if (i >= NN) return;
    int end = g_rows[i + 1] + g_bsum[i / SB];
    g_rows[i + 1] = end;
    g_cur[i] = end - g_deg[i];
    if (i == 0) g_rows[0] = 0;
}

__global__ void scatter_k(const int* __restrict__ src, const int* __restrict__ dst)
{
    int e = blockIdx.x * blockDim.x + threadIdx.x;
    if (e >= E2V) return;
    int s, d;
    if (e < EE) { s = src[e]; d = dst[e]; } else { s = d = e - EE; }
    int pos = atomicAdd(&g_cur[d], 1);
    g_colsrc[pos] = s;
}

// ===========================================================================
// Attention dot products
// ===========================================================================
__global__ void dots_k(const float* __restrict__ att_s, const float* __restrict__ att_d,
                       int N, int H, int C)
{
    int i = blockIdx.x * blockDim.x + threadIdx.x;
    if (i >= N * H) return;
    int n = i / H, hh = i % H;
    const float* hp = g_h + (size_t)n * H * C + hh * C;
    const float* as = att_s + hh * C;
    const float* ad = att_d + hh * C;
    float s = 0.f, d = 0.f;
    for (int c = 0; c < C; c++) {
        float v = hp[c];
        s = fmaf(v, as[c], s);
        d = fmaf(v, ad[c], d);
    }
    g_asrc[i] = s;
    g_adst[i] = d;
}

// ===========================================================================
// Fused softmax+aggregation, 8 heads x 32 ch, warp per dst node, 2 passes:
// pass1: per-head max; pass2: unnormalized exp-weighted aggregation + sum,
// normalize once at the end. No edge scratch buffer.
// ===========================================================================
__global__ void __launch_bounds__(256) gat_fused8_k(const float* __restrict__ bias, int relu)
{
    int w = (blockIdx.x * blockDim.x + threadIdx.x) >> 5;
    int lane = threadIdx.x & 31;
    if (w >= NN) return;
    int d = w;
    int beg = g_rows[d], end = g_rows[d + 1];

    float adl = (lane < 8) ? g_adst[d * 8 + lane] : 0.f;
    float ad[8];
    #pragma unroll
    for (int h = 0; h < 8; h++) ad[h] = __shfl_sync(0xffffffffu, adl, h);

    // ---- pass 1: per-head max (lanes stride over edges) ----
    float mx[8];
    #pragma unroll
    for (int h = 0; h < 8; h++) mx[h] = -INFINITY;
    for (int p = beg + lane; p < end; p += 32) {
        int s = __ldg(&g_colsrc[p]);
        const float4* ap = (const float4*)(g_asrc + s * 8);
        float4 a0 = __ldg(ap), a1 = __ldg(ap + 1);
        float e[8] = {a0.x + ad[0], a0.y + ad[1], a0.z + ad[2], a0.w + ad[3],
                      a1.x + ad[4], a1.y + ad[5], a1.z + ad[6], a1.w + ad[7]};
        #pragma unroll
        for (int h = 0; h < 8; h++) {
            e[h] = e[h] > 0.f ? e[h] : 0.2f * e[h];
            mx[h] = fmaxf(mx[h], e[h]);
        }
    }
    #pragma unroll
    for (int h = 0; h < 8; h++)
        #pragma unroll
        for (int o = 16; o; o >>= 1)
            mx[h] = fmaxf(mx[h], __shfl_xor_sync(0xffffffffu, mx[h], o));

    float mxl = (lane < 8) ? mx[lane] : 0.f;   // this lane's head max
    float adh = adl;                            // this lane's head a_dst

    // ---- pass 2: fused exp + sum + aggregate; lane owns channel `lane` ----
    float acc[8];
    #pragma unroll
    for (int h = 0; h < 8; h++) acc[h] = 0.f;
    float sml = 0.f;   // per-head sum, valid in lanes 0-7

    int p = beg;
    for (; p + 1 < end; p += 2) {
        int s0 = __ldg(&g_colsrc[p]);
        int s1 = __ldg(&g_colsrc[p + 1]);
        float ex0 = 0.f, ex1 = 0.f;
        if (lane < 8) {
            float e0 = __ldg(&g_asrc[s0 * 8 + lane]) + adh;
            float e1 = __ldg(&g_asrc[s1 * 8 + lane]) + adh;
            e0 = e0 > 0.f ? e0 : 0.2f * e0;
            e1 = e1 > 0.f ? e1 : 0.2f * e1;
            ex0 = __expf(e0 - mxl);
            ex1 = __expf(e1 - mxl);
            sml += ex0 + ex1;
        }
        const float* hp0 = g_h + (size_t)s0 * F1;
        const float* hp1 = g_h + (size_t)s1 * F1;
        #pragma unroll
        for (int h = 0; h < 8; h++) {
            float a0 = __shfl_sync(0xffffffffu, ex0, h);
            float a1 = __shfl_sync(0xffffffffu, ex1, h);
            acc[h] = fmaf(a0, __ldg(&hp0[h * 32 + lane]), acc[h]);
            acc[h] = fmaf(a1, __ldg(&hp1[h * 32 + lane]), acc[h]);
        }
    }
    if (p < end) {
        int s0 = __ldg(&g_colsrc[p]);
        float ex0 = 0.f;
        if (lane < 8) {
            float e0 = __ldg(&g_asrc[s0 * 8 + lane]) + adh;
            e0 = e0 > 0.f ? e0 : 0.2f * e0;
            ex0 = __expf(e0 - mxl);
            sml += ex0;
        }
        const float* hp0 = g_h + (size_t)s0 * F1;
        #pragma unroll
        for (int h = 0; h < 8; h++) {
            float a0 = __shfl_sync(0xffffffffu, ex0, h);
            acc[h] = fmaf(a0, __ldg(&hp0[h * 32 + lane]), acc[h]);
        }
    }

    float invl = 1.f / (sml + 1e-16f);   // valid in lanes 0-7
    float* op = g_out + (size_t)d * F1;
    #pragma unroll
    for (int h = 0; h < 8; h++) {
        float inv = __shfl_sync(0xffffffffu, invl, h);
        float v = acc[h] * inv + bias[h * 32 + lane];
        if (relu) v = fmaxf(v, 0.f);
        op[h * 32 + lane] = v;
    }
}

// ===========================================================================
// Fused layer-3: 1 head x 40 ch + bias + log_softmax, 2 passes, no scratch
// ===========================================================================
__global__ void __launch_bounds__(256) gat_fused1_k(const float* __restrict__ bias,
                                                    float* __restrict__ out)
{
    int w = (blockIdx.x * blockDim.x + threadIdx.x) >> 5;
    int lane = threadIdx.x & 31;
    if (w >= NN) return;
    int d = w;
    int beg = g_rows[d], end = g_rows[d + 1];
    float add = g_adst[d];

    float mx = -INFINITY;
    for (int p = beg + lane; p < end; p += 32) {
        int s = __ldg(&g_colsrc[p]);
        float e = __ldg(&g_asrc[s]) + add;
        e = e > 0.f ? e : 0.2f * e;
        mx = fmaxf(mx, e);
    }
    #pragma unroll
    for (int o = 16; o; o >>= 1) mx = fmaxf(mx, __shfl_xor_sync(0xffffffffu, mx, o));

    float a0 = 0.f, a1 = 0.f, sm = 0.f;
    for (int p = beg; p < end; p++) {
        int s = __ldg(&g_colsrc[p]);
        float e = __ldg(&g_asrc[s]) + add;   // broadcast load, same in all lanes
        e = e > 0.f ? e : 0.2f * e;
        float ex = __expf(e - mx);
        sm += ex;
        const float* hp = g_h + (size_t)s * OUTC;
        a0 = fmaf(ex, __ldg(&hp[lane]), a0);
        if (lane < 8) a1 = fmaf(ex, __ldg(&hp[lane + 32]), a1);
    }
    float inv = 1.f / (sm + 1e-16f);

    float v0 = a0 * inv + bias[lane];
    float v1 = (lane < 8) ? a1 * inv + bias[lane + 32] : -INFINITY;
    float m = fmaxf(v0, v1);
    #pragma unroll
    for (int o = 16; o; o >>= 1) m = fmaxf(m, __shfl_xor_sync(0xffffffffu, m, o));
    float s2 = __expf(v0 - m) + ((lane < 8) ? __expf(v1 - m) : 0.f);
    #pragma unroll
    for (int o = 16; o; o >>= 1) s2 += __shfl_xor_sync(0xffffffffu, s2, o);
    float lg = m + logf(s2);
    out[(size_t)d * OUTC + lane] = v0 - lg;
    if (lane < 8) out[(size_t)d * OUTC + lane + 32] = v1 - lg;
}

// ===========================================================================
// TF32 tensor-core GEMM with cp.async 2-stage double buffering.
// g_h = A[M,K] @ B[K,Ncol]; 128x64x16 block, 8 warps (4x2), m16n8k8 tf32.
// fp32 fed directly to mma (HW truncates to tf32).
// ===========================================================================
#define GBM 128
#define GBN 64
#define GBK 16
#define AS_STRIDE 20   // 16 + 4 pad (row start 80B: 16B-aligned)
#define BS_STRIDE 72   // 64 + 8 pad (row start 288B: 16B-aligned)

__device__ __forceinline__ void cp16(uint32_t dst, const void* src, int valid)
{
    asm volatile("cp.async.ca.shared.global [%0], [%1], 16, %2;\n"
                 :: "r"(dst), "l"(src), "r"(valid ? 16 : 0));
}

__device__ __forceinline__ void mma1688(float* c, const uint32_t* a, const uint32_t* b)
{
    asm volatile(
        "mma.sync.aligned.m16n8k8.row.col.f32.tf32.tf32.f32 "
        "{%0,%1,%2,%3},{%4,%5,%6,%7},{%8,%9},{%0,%1,%2,%3};"
        : "+f"(c[0]), "+f"(c[1]), "+f"(c[2]), "+f"(c[3])
        : "r"(a[0]), "r"(a[1]), "r"(a[2]), "r"(a[3]), "r"(b[0]), "r"(b[1]));
}

__global__ void __launch_bounds__(256) tf32gemm_k(const float* __restrict__ Aext,
                                                  const float* __restrict__ B,
                                                  int M, int Ncol, int K, int a_internal)
{
    const float* A = a_internal ? g_out : Aext;
    __shared__ float As[2][GBM * AS_STRIDE];
    __shared__ float Bs[2][GBK * BS_STRIDE];

    int tid  = threadIdx.x;
    int warp = tid >> 5;
    int lane = tid & 31;
    int wm = warp >> 1;
    int wn = warp & 1;
    int bm = blockIdx.y * GBM;
    int bn = blockIdx.x * GBN;
    int lr = lane >> 2;
    int lc = lane & 3;

    // per-thread load coordinates
    int ar0 = tid >> 2;                 // A rows for the 2 float4s
    int ac  = (tid & 3) * 4;
    int br  = tid >> 4;                 // B row
    int bc  = (tid & 15) * 4;

    uint32_t as_base = (uint32_t)__cvta_generic_to_shared(&As[0][0]);
    uint32_t bs_base = (uint32_t)__cvta_generic_to_shared(&Bs[0][0]);
    const uint32_t AS_BYTES = GBM * AS_STRIDE * 4;
    const uint32_t BS_BYTES = GBK * BS_STRIDE * 4;

    int niter = K / GBK;

    // prologue: stage 0
    {
        int k0 = 0;
        #pragma unroll
        for (int i = 0; i < 2; i++) {
            int r = ar0 + i * 64;
            int gr = bm + r;
            int ok = gr < M;
            const float* src = A + (size_t)(ok ? gr : 0) * K + k0 + ac;
            cp16(as_base + (r * AS_STRIDE + ac) * 4, src, ok);
        }
        {
            int gc = bn + bc;
            int ok = gc < Ncol;
            const float* src = B + (size_t)(k0 + br) * Ncol + (ok ? gc : 0);
            cp16(bs_base + (br * BS_STRIDE + bc) * 4, src, ok);
        }
        asm volatile("cp.async.commit_group;\n" ::);
    }

    float c[2][4][4];
    #pragma unroll
    for (int i = 0; i < 2; i++)
        #pragma unroll
        for (int j = 0; j < 4; j++)
            #pragma unroll
            for (int r = 0; r < 4; r++) c[i][j][r] = 0.f;

    int buf = 0;
    for (int it = 0; it < niter; it++) {
        int has_next = (it + 1 < niter);
        if (has_next) {
            int k0 = (it + 1) * GBK;
            uint32_t ab = as_base + (buf ^ 1) * AS_BYTES;
            uint32_t bb = bs_base + (buf ^ 1) * BS_BYTES;
            #pragma unroll
            for (int i = 0; i < 2; i++) {
                int r = ar0 + i * 64;
                int gr = bm + r;
                int ok = gr < M;
                const float* src = A + (size_t)(ok ? gr : 0) * K + k0 + ac;
                cp16(ab + (r * AS_STRIDE + ac) * 4, src, ok);
            }
            {
                int gc = bn + bc;
                int ok = gc < Ncol;
                const float* src = B + (size_t)(k0 + br) * Ncol + (ok ? gc : 0);
                cp16(bb + (br * BS_STRIDE + bc) * 4, src, ok);
            }
            asm volatile("cp.async.commit_group;\n" ::);
            asm volatile("cp.async.wait_group 1;\n" ::);
        } else {
            asm volatile("cp.async.wait_group 0;\n" ::);
        }
        __syncthreads();

        const float* Asb = As[buf];
        const float* Bsb = Bs[buf];
        #pragma unroll
        for (int kk = 0; kk < GBK; kk += 8) {
            uint32_t afrag[2][4], bfrag[4][2];
            #pragma unroll
            for (int i = 0; i < 2; i++) {
                int rb = wm * 32 + i * 16;
                afrag[i][0] = __float_as_uint(Asb[(rb + lr)     * AS_STRIDE + kk + lc]);
                afrag[i][1] = __float_as_uint(Asb[(rb + 8 + lr) * AS_STRIDE + kk + lc]);
                afrag[i][2] = __float_as_uint(Asb[(rb + lr)     * AS_STRIDE + kk + 4 + lc]);
                afrag[i][3] = __float_as_uint(Asb[(rb + 8 + lr) * AS_STRIDE + kk + 4 + lc]);
            }
            #pragma unroll
            for (int j = 0; j < 4; j++) {
                int nb = wn * 32 + j * 8;
                bfrag[j][0] = __float_as_uint(Bsb[(kk + lc)     * BS_STRIDE + nb + lr]);
                bfrag[j][1] = __float_as_uint(Bsb[(kk + 4 + lc) * BS_STRIDE + nb + lr]);
            }
            #pragma unroll
            for (int i = 0; i < 2; i++)
                #pragma unroll
                for (int j = 0; j < 4; j++)
                    mma1688(c[i][j], afrag[i], bfrag[j]);
        }
        __syncthreads();
        buf ^= 1;
    }

    #pragma unroll
    for (int i = 0; i < 2; i++) {
        int r0 = bm + wm * 32 + i * 16 + lr;
        #pragma unroll
        for (int j = 0; j < 4; j++) {
            int col = bn + wn * 32 + j * 8 + lc * 2;
            if (col < Ncol) {
                if (r0 < M) {
                    g_h[(size_t)r0 * Ncol + col]     = c[i][j][0];
                    g_h[(size_t)r0 * Ncol + col + 1] = c[i][j][1];
                }
                if (r0 + 8 < M) {
                    g_h[(size_t)(r0 + 8) * Ncol + col]     = c[i][j][2];
                    g_h[(size_t)(r0 + 8) * Ncol + col + 1] = c[i][j][3];
                }
            }
        }
    }
}

// ===========================================================================
// Launcher
// ===========================================================================
extern "C" void kernel_launch(void* const* d_in, const int* in_sizes, int n_in,
                              void* d_out, int out_size)
{
    const float* x    = (const float*)d_in[0];
    const int*   ei   = (const int*)  d_in[1];
    const int*   srcv = ei;
    const int*   dstv = ei + EE;
    const float* W1  = (const float*)d_in[2];
    const float* as1 = (const float*)d_in[3];
    const float* ad1 = (const float*)d_in[4];
    const float* b1  = (const float*)d_in[5];
    const float* W2  = (const float*)d_in[6];
    const float* as2 = (const float*)d_in[7];
    const float* ad2 = (const float*)d_in[8];
    const float* b2  = (const float*)d_in[9];
    const float* W3  = (const float*)d_in[10];
    const float* as3 = (const float*)d_in[11];
    const float* ad3 = (const float*)d_in[12];
    const float* b3  = (const float*)d_in[13];
    float* out = (float*)d_out;

    dim3 blk(256);
    dim3 gemm_g1((F1 + GBN - 1) / GBN,   (NN + GBM - 1) / GBM);
    dim3 gemm_g3((OUTC + GBN - 1) / GBN, (NN + GBM - 1) / GBM);
    int nbN    = (NN + 255) / 256;
    int nbE    = (EE + 255) / 256;
    int nbE2   = (E2V + 255) / 256;
    int nbNH   = (NN * 8 + 255) / 256;
    int nbWarp = (NN * 32 + 255) / 256;

    // ---- CSR build ----
    init_deg_k<<<nbN, blk>>>();
    count_k<<<nbE, blk>>>(dstv);
    scan1_k<<<NBLK, SB>>>();
    scan2_k<<<1, 128>>>();
    scan3_k<<<nbN, blk>>>();
    scatter_k<<<nbE2, blk>>>(srcv, dstv);

    // ---- layer 1: 128 -> 8x32 ----
    tf32gemm_k<<<gemm_g1, blk>>>(x, W1, NN, F1, 128, 0);
    dots_k<<<nbNH, blk>>>(as1, ad1, NN, 8, 32);
    gat_fused8_k<<<nbWarp, blk>>>(b1, 1);

    // ---- layer 2: 256 -> 8x32 ----
    tf32gemm_k<<<gemm_g1, blk>>>(nullptr, W2, NN, F1, F1, 1);
    dots_k<<<nbNH, blk>>>(as2, ad2, NN, 8, 32);
    gat_fused8_k<<<nbWarp, blk>>>(b2, 1);

    // ---- layer 3: 256 -> 40 + log_softmax ----
    tf32gemm_k<<<gemm_g3, blk>>>(nullptr, W3, NN, OUTC, F1, 1);
    dots_k<<<nbN, blk>>>(as3, ad3, NN, 1, OUTC);
    gat_fused1_k<<<nbWarp, blk>>>(b3, out);
}

// round 7
// speedup vs baseline: 1.0566x; 1.0566x over previous
#include <cuda_runtime.h>
#include <math.h>
#include <stdint.h>

#define NN   50000
#define EE   800000
#define E2V  (EE + NN)
#define F1   256
#define OUTC 40
#define SB   512
#define NBLK ((NN + SB - 1) / SB)

// ---- scratch ----
__device__ float g_h   [(size_t)NN * F1];
__device__ float g_out [(size_t)NN * F1];
__device__ float g_asrc[NN * 8];
__device__ float g_adst[NN * 8];
__device__ float g_e   [(size_t)E2V * 8];
__device__ int   g_deg [NN];
__device__ int   g_rows[NN + 1];
__device__ int   g_cur [NN];
__device__ int   g_colsrc[E2V];
__device__ int   g_bsum[NBLK + 1];

// ===========================================================================
// CSR build (dst-grouped): count -> scan -> scatter
// ===========================================================================
__global__ void init_deg_k()
{
    int i = blockIdx.x * blockDim.x + threadIdx.x;
    if (i < NN) g_deg[i] = 1;
}

__global__ void count_k(const int* __restrict__ dst)
{
    int e = blockIdx.x * blockDim.x + threadIdx.x;
    if (e < EE) atomicAdd(&g_deg[dst[e]], 1);
}

__global__ void scan1_k()
{
    __shared__ int sh[SB];
    int i = blockIdx.x * SB + threadIdx.x;
    sh[threadIdx.x] = (i < NN) ? g_deg[i] : 0;
    __syncthreads();
    #pragma unroll
    for (int o = 1; o < SB; o <<= 1) {
        int t = (threadIdx.x >= o) ? sh[threadIdx.x - o] : 0;
        __syncthreads();
        sh[threadIdx.x] += t;
        __syncthreads();
    }
    if (i < NN) g_rows[i + 1] = sh[threadIdx.x];
    if (threadIdx.x == SB - 1) g_bsum[blockIdx.x] = sh[SB - 1];
}

__global__ void scan2_k()
{
    __shared__ int sh[128];
    int t = threadIdx.x;
    int v = (t < NBLK) ? g_bsum[t] : 0;
    sh[t] = v;
    __syncthreads();
    #pragma unroll
    for (int o = 1; o < 128; o <<= 1) {
        int u = (t >= o) ? sh[t - o] : 0;
        __syncthreads();
        sh[t] += u;
        __syncthreads();
    }
    if (t < NBLK) g_bsum[t] = sh[t] - v;   // exclusive
}

__global__ void scan3_k()
{
    int i = blockIdx.x * blockDim.x + threadIdx.x;
    if (i >= NN) return;
    int end = g_rows[i + 1] + g_bsum[i / SB];
    g_rows[i + 1] = end;
    g_cur[i] = end - g_deg[i];
    if (i == 0) g_rows[0] = 0;
}

__global__ void scatter_k(const int* __restrict__ src, const int* __restrict__ dst)
{
    int e = blockIdx.x * blockDim.x + threadIdx.x;
    if (e >= E2V) return;
    int s, d;
    if (e < EE) { s = src[e]; d = dst[e]; } else { s = d = e - EE; }
    int pos = atomicAdd(&g_cur[d], 1);
    g_colsrc[pos] = s;
}

// ===========================================================================
// Attention dot products
// ===========================================================================
__global__ void dots_k(const float* __restrict__ att_s, const float* __restrict__ att_d,
                       int N, int H, int C)
{
    int i = blockIdx.x * blockDim.x + threadIdx.x;
    if (i >= N * H) return;
    int n = i / H, hh = i % H;
    const float* hp = g_h + (size_t)n * H * C + hh * C;
    const float* as = att_s + hh * C;
    const float* ad = att_d + hh * C;
    float s = 0.f, d = 0.f;
    for (int c = 0; c < C; c++) {
        float v = hp[c];
        s = fmaf(v, as[c], s);
        d = fmaf(v, ad[c], d);
    }
    g_asrc[i] = s;
    g_adst[i] = d;
}

// ===========================================================================
// Fused per-node softmax + aggregation, 8 heads x 32 ch. Warp per dst node.
// 3 passes with per-edge exp cached in g_e (R4 design); pass 3 unrolled x2.
// ===========================================================================
__global__ void __launch_bounds__(256) gat_fused8_k(const float* __restrict__ bias, int relu)
{
    int w = (blockIdx.x * blockDim.x + threadIdx.x) >> 5;
    int lane = threadIdx.x & 31;
    if (w >= NN) return;
    int d = w;
    int beg = g_rows[d], end = g_rows[d + 1];

    float adl = (lane < 8) ? g_adst[d * 8 + lane] : 0.f;
    float ad[8];
    #pragma unroll
    for (int h = 0; h < 8; h++) ad[h] = __shfl_sync(0xffffffffu, adl, h);

    // pass 1: e = leaky(asrc[s]+adst[d]), store, per-head max
    float mx[8];
    #pragma unroll
    for (int h = 0; h < 8; h++) mx[h] = -INFINITY;
    for (int p = beg + lane; p < end; p += 32) {
        int s = __ldg(&g_colsrc[p]);
        const float4* ap = (const float4*)(g_asrc + s * 8);
        float4 a0 = __ldg(ap), a1 = __ldg(ap + 1);
        float e[8] = {a0.x + ad[0], a0.y + ad[1], a0.z + ad[2], a0.w + ad[3],
                      a1.x + ad[4], a1.y + ad[5], a1.z + ad[6], a1.w + ad[7]};
        #pragma unroll
        for (int h = 0; h < 8; h++) {
            e[h] = e[h] > 0.f ? e[h] : 0.2f * e[h];
            mx[h] = fmaxf(mx[h], e[h]);
        }
        float4* ep = (float4*)(g_e + (size_t)p * 8);
        ep[0] = make_float4(e[0], e[1], e[2], e[3]);
        ep[1] = make_float4(e[4], e[5], e[6], e[7]);
    }
    #pragma unroll
    for (int h = 0; h < 8; h++)
        #pragma unroll
        for (int o = 16; o; o >>= 1)
            mx[h] = fmaxf(mx[h], __shfl_xor_sync(0xffffffffu, mx[h], o));

    // pass 2: exp in place + per-head sum
    float sm[8];
    #pragma unroll
    for (int h = 0; h < 8; h++) sm[h] = 0.f;
    for (int p = beg + lane; p < end; p += 32) {
        float4* ep = (float4*)(g_e + (size_t)p * 8);
        float4 e0 = ep[0], e1 = ep[1];
        float ex[8] = {__expf(e0.x - mx[0]), __expf(e0.y - mx[1]),
                       __expf(e0.z - mx[2]), __expf(e0.w - mx[3]),
                       __expf(e1.x - mx[4]), __expf(e1.y - mx[5]),
                       __expf(e1.z - mx[6]), __expf(e1.w - mx[7])};
        #pragma unroll
        for (int h = 0; h < 8; h++) sm[h] += ex[h];
        ep[0] = make_float4(ex[0], ex[1], ex[2], ex[3]);
        ep[1] = make_float4(ex[4], ex[5], ex[6], ex[7]);
    }
    #pragma unroll
    for (int h = 0; h < 8; h++)
        #pragma unroll
        for (int o = 16; o; o >>= 1)
            sm[h] += __shfl_xor_sync(0xffffffffu, sm[h], o);

    float inv[8];
    #pragma unroll
    for (int h = 0; h < 8; h++) inv[h] = 1.f / (sm[h] + 1e-16f);

    // pass 3: aggregate, unrolled x2 for gather MLP
    float acc[8];
    #pragma unroll
    for (int h = 0; h < 8; h++) acc[h] = 0.f;
    int p = beg;
    for (; p + 1 < end; p += 2) {
        int s0 = __ldg(&g_colsrc[p]);
        int s1 = __ldg(&g_colsrc[p + 1]);
        const float4* ep0 = (const float4*)(g_e + (size_t)p * 8);
        const float4* ep1 = (const float4*)(g_e + (size_t)(p + 1) * 8);
        float4 ea0 = __ldg(ep0), ea1 = __ldg(ep0 + 1);
        float4 eb0 = __ldg(ep1), eb1 = __ldg(ep1 + 1);
        const float* hp0 = g_h + (size_t)s0 * F1;
        const float* hp1 = g_h + (size_t)s1 * F1;
        float w0[8] = {ea0.x, ea0.y, ea0.z, ea0.w, ea1.x, ea1.y, ea1.z, ea1.w};
        float w1[8] = {eb0.x, eb0.y, eb0.z, eb0.w, eb1.x, eb1.y, eb1.z, eb1.w};
        #pragma unroll
        for (int h = 0; h < 8; h++) {
            acc[h] = fmaf(w0[h], __ldg(&hp0[h * 32 + lane]), acc[h]);
            acc[h] = fmaf(w1[h], __ldg(&hp1[h * 32 + lane]), acc[h]);
        }
    }
    if (p < end) {
        int s0 = __ldg(&g_colsrc[p]);
        const float4* ep0 = (const float4*)(g_e + (size_t)p * 8);
        float4 ea0 = __ldg(ep0), ea1 = __ldg(ep0 + 1);
        const float* hp0 = g_h + (size_t)s0 * F1;
        float w0[8] = {ea0.x, ea0.y, ea0.z, ea0.w, ea1.x, ea1.y, ea1.z, ea1.w};
        #pragma unroll
        for (int h = 0; h < 8; h++)
            acc[h] = fmaf(w0[h], __ldg(&hp0[h * 32 + lane]), acc[h]);
    }

    float* op = g_out + (size_t)d * F1;
    #pragma unroll
    for (int h = 0; h < 8; h++) {
        float v = acc[h] * inv[h] + bias[h * 32 + lane];
        if (relu) v = fmaxf(v, 0.f);
        op[h * 32 + lane] = v;
    }
}

// ===========================================================================
// Fused layer-3: 1 head x 40 ch + bias + log_softmax, warp per node
// ===========================================================================
__global__ void __launch_bounds__(256) gat_fused1_k(const float* __restrict__ bias,
                                                    float* __restrict__ out)
{
    int w = (blockIdx.x * blockDim.x + threadIdx.x) >> 5;
    int lane = threadIdx.x & 31;
    if (w >= NN) return;
    int d = w;
    int beg = g_rows[d], end = g_rows[d + 1];
    float add = g_adst[d];

    float mx = -INFINITY;
    for (int p = beg + lane; p < end; p += 32) {
        int s = __ldg(&g_colsrc[p]);
        float e = __ldg(&g_asrc[s]) + add;
        e = e > 0.f ? e : 0.2f * e;
        g_e[p] = e;
        mx = fmaxf(mx, e);
    }
    #pragma unroll
    for (int o = 16; o; o >>= 1) mx = fmaxf(mx, __shfl_xor_sync(0xffffffffu, mx, o));

    float sm = 0.f;
    for (int p = beg + lane; p < end; p += 32) {
        float ex = __expf(g_e[p] - mx);
        g_e[p] = ex;
        sm += ex;
    }
    #pragma unroll
    for (int o = 16; o; o >>= 1) sm += __shfl_xor_sync(0xffffffffu, sm, o);
    float inv = 1.f / (sm + 1e-16f);

    // aggregate, unrolled x2
    float a0 = 0.f, a1 = 0.f;
    int p = beg;
    for (; p + 1 < end; p += 2) {
        int s0 = __ldg(&g_colsrc[p]);
        int s1 = __ldg(&g_colsrc[p + 1]);
        float al0 = __ldg(&g_e[p]);
        float al1 = __ldg(&g_e[p + 1]);
        const float* hp0 = g_h + (size_t)s0 * OUTC;
        const float* hp1 = g_h + (size_t)s1 * OUTC;
        a0 = fmaf(al0, __ldg(&hp0[lane]), a0);
        a0 = fmaf(al1, __ldg(&hp1[lane]), a0);
        if (lane < 8) {
            a1 = fmaf(al0, __ldg(&hp0[lane + 32]), a1);
            a1 = fmaf(al1, __ldg(&hp1[lane + 32]), a1);
        }
    }
    if (p < end) {
        int s0 = __ldg(&g_colsrc[p]);
        float al0 = __ldg(&g_e[p]);
        const float* hp0 = g_h + (size_t)s0 * OUTC;
        a0 = fmaf(al0, __ldg(&hp0[lane]), a0);
        if (lane < 8) a1 = fmaf(al0, __ldg(&hp0[lane + 32]), a1);
    }

    float v0 = a0 * inv + bias[lane];
    float v1 = (lane < 8) ? a1 * inv + bias[lane + 32] : -INFINITY;
    float m = fmaxf(v0, v1);
    #pragma unroll
    for (int o = 16; o; o >>= 1) m = fmaxf(m, __shfl_xor_sync(0xffffffffu, m, o));
    float s2 = __expf(v0 - m) + ((lane < 8) ? __expf(v1 - m) : 0.f);
    #pragma unroll
    for (int o = 16; o; o >>= 1) s2 += __shfl_xor_sync(0xffffffffu, s2, o);
    float lg = m + logf(s2);
    out[(size_t)d * OUTC + lane] = v0 - lg;
    if (lane < 8) out[(size_t)d * OUTC + lane + 32] = v1 - lg;
}

// ===========================================================================
// TF32 tensor-core GEMM with cp.async 2-stage double buffering.
// ===========================================================================
#define GBM 128
#define GBN 64
#define GBK 16
#define AS_STRIDE 20   // 16 + 4 pad
#define BS_STRIDE 72   // 64 + 8 pad

__device__ __forceinline__ void cp16(uint32_t dst, const void* src, int valid)
{
    asm volatile("cp.async.ca.shared.global [%0], [%1], 16, %2;\n"
                 :: "r"(dst), "l"(src), "r"(valid ? 16 : 0));
}

__device__ __forceinline__ void mma1688(float* c, const uint32_t* a, const uint32_t* b)
{
    asm volatile(
        "mma.sync.aligned.m16n8k8.row.col.f32.tf32.tf32.f32 "
        "{%0,%1,%2,%3},{%4,%5,%6,%7},{%8,%9},{%0,%1,%2,%3};"
        : "+f"(c[0]), "+f"(c[1]), "+f"(c[2]), "+f"(c[3])
        : "r"(a[0]), "r"(a[1]), "r"(a[2]), "r"(a[3]), "r"(b[0]), "r"(b[1]));
}

__global__ void __launch_bounds__(256) tf32gemm_k(const float* __restrict__ Aext,
                                                  const float* __restrict__ B,
                                                  int M, int Ncol, int K, int a_internal)
{
    const float* A = a_internal ? g_out : Aext;
    __shared__ float As[2][GBM * AS_STRIDE];
    __shared__ float Bs[2][GBK * BS_STRIDE];

    int tid  = threadIdx.x;
    int warp = tid >> 5;
    int lane = tid & 31;
    int wm = warp >> 1;
    int wn = warp & 1;
    int bm = blockIdx.y * GBM;
    int bn = blockIdx.x * GBN;
    int lr = lane >> 2;
    int lc = lane & 3;

    int ar0 = tid >> 2;
    int ac  = (tid & 3) * 4;
    int br  = tid >> 4;
    int bc  = (tid & 15) * 4;

    uint32_t as_base = (uint32_t)__cvta_generic_to_shared(&As[0][0]);
    uint32_t bs_base = (uint32_t)__cvta_generic_to_shared(&Bs[0][0]);
    const uint32_t AS_BYTES = GBM * AS_STRIDE * 4;
    const uint32_t BS_BYTES = GBK * BS_STRIDE * 4;

    int niter = K / GBK;

    {
        int k0 = 0;
        #pragma unroll
        for (int i = 0; i < 2; i++) {
            int r = ar0 + i * 64;
            int gr = bm + r;
            int ok = gr < M;
            const float* src = A + (size_t)(ok ? gr : 0) * K + k0 + ac;
            cp16(as_base + (r * AS_STRIDE + ac) * 4, src, ok);
        }
        {
            int gc = bn + bc;
            int ok = gc < Ncol;
            const float* src = B + (size_t)(k0 + br) * Ncol + (ok ? gc : 0);
            cp16(bs_base + (br * BS_STRIDE + bc) * 4, src, ok);
        }
        asm volatile("cp.async.commit_group;\n" ::);
    }

    float c[2][4][4];
    #pragma unroll
    for (int i = 0; i < 2; i++)
        #pragma unroll
        for (int j = 0; j < 4; j++)
            #pragma unroll
            for (int r = 0; r < 4; r++) c[i][j][r] = 0.f;

    int buf = 0;
    for (int it = 0; it < niter; it++) {
        int has_next = (it + 1 < niter);
        if (has_next) {
            int k0 = (it + 1) * GBK;
            uint32_t ab = as_base + (buf ^ 1) * AS_BYTES;
            uint32_t bb = bs_base + (buf ^ 1) * BS_BYTES;
            #pragma unroll
            for (int i = 0; i < 2; i++) {
                int r = ar0 + i * 64;
                int gr = bm + r;
                int ok = gr < M;
                const float* src = A + (size_t)(ok ? gr : 0) * K + k0 + ac;
                cp16(ab + (r * AS_STRIDE + ac) * 4, src, ok);
            }
            {
                int gc = bn + bc;
                int ok = gc < Ncol;
                const float* src = B + (size_t)(k0 + br) * Ncol + (ok ? gc : 0);
                cp16(bb + (br * BS_STRIDE + bc) * 4, src, ok);
            }
            asm volatile("cp.async.commit_group;\n" ::);
            asm volatile("cp.async.wait_group 1;\n" ::);
        } else {
            asm volatile("cp.async.wait_group 0;\n" ::);
        }
        __syncthreads();

        const float* Asb = As[buf];
        const float* Bsb = Bs[buf];
        #pragma unroll
        for (int kk = 0; kk < GBK; kk += 8) {
            uint32_t afrag[2][4], bfrag[4][2];
            #pragma unroll
            for (int i = 0; i < 2; i++) {
                int rb = wm * 32 + i * 16;
                afrag[i][0] = __float_as_uint(Asb[(rb + lr)     * AS_STRIDE + kk + lc]);
                afrag[i][1] = __float_as_uint(Asb[(rb + 8 + lr) * AS_STRIDE + kk + lc]);
                afrag[i][2] = __float_as_uint(Asb[(rb + lr)     * AS_STRIDE + kk + 4 + lc]);
                afrag[i][3] = __float_as_uint(Asb[(rb + 8 + lr) * AS_STRIDE + kk + 4 + lc]);
            }
            #pragma unroll
            for (int j = 0; j < 4; j++) {
                int nb = wn * 32 + j * 8;
                bfrag[j][0] = __float_as_uint(Bsb[(kk + lc)     * BS_STRIDE + nb + lr]);
                bfrag[j][1] = __float_as_uint(Bsb[(kk + 4 + lc) * BS_STRIDE + nb + lr]);
            }
            #pragma unroll
            for (int i = 0; i < 2; i++)
                #pragma unroll
                for (int j = 0; j < 4; j++)
                    mma1688(c[i][j], afrag[i], bfrag[j]);
        }
        __syncthreads();
        buf ^= 1;
    }

    #pragma unroll
    for (int i = 0; i < 2; i++) {
        int r0 = bm + wm * 32 + i * 16 + lr;
        #pragma unroll
        for (int j = 0; j < 4; j++) {
            int col = bn + wn * 32 + j * 8 + lc * 2;
            if (col < Ncol) {
                if (r0 < M) {
                    g_h[(size_t)r0 * Ncol + col]     = c[i][j][0];
                    g_h[(size_t)r0 * Ncol + col + 1] = c[i][j][1];
                }
                if (r0 + 8 < M) {
                    g_h[(size_t)(r0 + 8) * Ncol + col]     = c[i][j][2];
                    g_h[(size_t)(r0 + 8) * Ncol + col + 1] = c[i][j][3];
                }
            }
        }
    }
}

// ===========================================================================
// Launcher
// ===========================================================================
extern "C" void kernel_launch(void* const* d_in, const int* in_sizes, int n_in,
                              void* d_out, int out_size)
{
    const float* x    = (const float*)d_in[0];
    const int*   ei   = (const int*)  d_in[1];
    const int*   srcv = ei;
    const int*   dstv = ei + EE;
    const float* W1  = (const float*)d_in[2];
    const float* as1 = (const float*)d_in[3];
    const float* ad1 = (const float*)d_in[4];
    const float* b1  = (const float*)d_in[5];
    const float* W2  = (const float*)d_in[6];
    const float* as2 = (const float*)d_in[7];
    const float* ad2 = (const float*)d_in[8];
    const float* b2  = (const float*)d_in[9];
    const float* W3  = (const float*)d_in[10];
    const float* as3 = (const float*)d_in[11];
    const float* ad3 = (const float*)d_in[12];
    const float* b3  = (const float*)d_in[13];
    float* out = (float*)d_out;

    dim3 blk(256);
    dim3 gemm_g1((F1 + GBN - 1) / GBN,   (NN + GBM - 1) / GBM);
    dim3 gemm_g3((OUTC + GBN - 1) / GBN, (NN + GBM - 1) / GBM);
    int nbN    = (NN + 255) / 256;
    int nbE    = (EE + 255) / 256;
    int nbE2   = (E2V + 255) / 256;
    int nbNH   = (NN * 8 + 255) / 256;
    int nbWarp = (NN * 32 + 255) / 256;

    // ---- CSR build ----
    init_deg_k<<<nbN, blk>>>();
    count_k<<<nbE, blk>>>(dstv);
    scan1_k<<<NBLK, SB>>>();
    scan2_k<<<1, 128>>>();
    scan3_k<<<nbN, blk>>>();
    scatter_k<<<nbE2, blk>>>(srcv, dstv);

    // ---- layer 1: 128 -> 8x32 ----
    tf32gemm_k<<<gemm_g1, blk>>>(x, W1, NN, F1, 128, 0);
    dots_k<<<nbNH, blk>>>(as1, ad1, NN, 8, 32);
    gat_fused8_k<<<nbWarp, blk>>>(b1, 1);

    // ---- layer 2: 256 -> 8x32 ----
    tf32gemm_k<<<gemm_g1, blk>>>(nullptr, W2, NN, F1, F1, 1);
    dots_k<<<nbNH, blk>>>(as2, ad2, NN, 8, 32);
    gat_fused8_k<<<nbWarp, blk>>>(b2, 1);

    // ---- layer 3: 256 -> 40 + log_softmax ----
    tf32gemm_k<<<gemm_g3, blk>>>(nullptr, W3, NN, OUTC, F1, 1);
    dots_k<<<nbN, blk>>>(as3, ad3, NN, 1, OUTC);
    gat_fused1_k<<<nbWarp, blk>>>(b3, out);
}

// round 8
// speedup vs baseline: 1.0850x; 1.0269x over previous
#include <cuda_runtime.h>
#include <math.h>
#include <stdint.h>

#define NN   50000
#define EE   800000
#define E2V  (EE + NN)
#define F1   256
#define OUTC 40
#define SB   512
#define NBLK ((NN + SB - 1) / SB)

// ---- scratch ----
__device__ float g_h   [(size_t)NN * F1];
__device__ float g_out [(size_t)NN * F1];
__device__ float g_asrc[NN * 8];
__device__ float g_adst[NN * 8];
__device__ float g_e   [(size_t)E2V * 8];
__device__ int   g_deg [NN];
__device__ int   g_rows[NN + 1];
__device__ int   g_cur [NN];
__device__ int   g_colsrc[E2V];
__device__ int   g_bsum[NBLK + 1];
__device__ float g_gmax[3][16];   // per layer: [0..7] = max a_src per head, [8..15] = max a_dst

// ===========================================================================
// Float atomic max (order-free, handles mixed signs; init to -inf)
// ===========================================================================
__device__ __forceinline__ void atomicMaxF(float* addr, float val)
{
    unsigned int u = __float_as_uint(val);
    if (u >> 31) atomicMin((unsigned int*)addr, u);
    else         atomicMax((int*)addr, (int)u);
}

// ===========================================================================
// CSR build (dst-grouped): count -> scan -> scatter
// ===========================================================================
__global__ void init_deg_k()
{
    int i = blockIdx.x * blockDim.x + threadIdx.x;
    if (i < NN) g_deg[i] = 1;
    if (i < 48) ((float*)g_gmax)[i] = __int_as_float(0xFF800000);
}

__global__ void count_k(const int* __restrict__ dst)
{
    int e = blockIdx.x * blockDim.x + threadIdx.x;
    if (e < EE) atomicAdd(&g_deg[dst[e]], 1);
}

__global__ void scan1_k()
{
    __shared__ int sh[SB];
    int i = blockIdx.x * SB + threadIdx.x;
    sh[threadIdx.x] = (i < NN) ? g_deg[i] : 0;
    __syncthreads();
    #pragma unroll
    for (int o = 1; o < SB; o <<= 1) {
        int t = (threadIdx.x >= o) ? sh[threadIdx.x - o] : 0;
        __syncthreads();
        sh[threadIdx.x] += t;
        __syncthreads();
    }
    if (i < NN) g_rows[i + 1] = sh[threadIdx.x];
    if (threadIdx.x == SB - 1) g_bsum[blockIdx.x] = sh[SB - 1];
}

__global__ void scan2_k()
{
    __shared__ int sh[128];
    int t = threadIdx.x;
    int v = (t < NBLK) ? g_bsum[t] : 0;
    sh[t] = v;
    __syncthreads();
    #pragma unroll
    for (int o = 1; o < 128; o <<= 1) {
        int u = (t >= o) ? sh[t - o] : 0;
        __syncthreads();
        sh[t] += u;
        __syncthreads();
    }
    if (t < NBLK) g_bsum[t] = sh[t] - v;   // exclusive
}

__global__ void scan3_k()
{
    int i = blockIdx.x * blockDim.x + threadIdx.x;
    if (i >= NN) return;
    int end = g_rows[i + 1] + g_bsum[i / SB];
    g_rows[i + 1] = end;
    g_cur[i] = end - g_deg[i];
    if (i == 0) g_rows[0] = 0;
}

__global__ void scatter_k(const int* __restrict__ src, const int* __restrict__ dst)
{
    int e = blockIdx.x * blockDim.x + threadIdx.x;
    if (e >= E2V) return;
    int s, d;
    if (e < EE) { s = src[e]; d = dst[e]; } else { s = d = e - EE; }
    int pos = atomicAdd(&g_cur[d], 1);
    g_colsrc[pos] = s;
}

// ===========================================================================
// Attention dot products + per-head global max (block reduce + atomicMax)
// ===========================================================================
template<int H>
__global__ void __launch_bounds__(256) dots_k(const float* __restrict__ att_s,
                                              const float* __restrict__ att_d,
                                              int C, int layer)
{
    __shared__ float rs[256], rd[256];
    int tid = threadIdx.x;
    int i = blockIdx.x * blockDim.x + tid;
    float s = -INFINITY, d = -INFINITY;
    if (i < NN * H) {
        int n = i / H, hh = i % H;
        const float* hp = g_h + (size_t)n * H * C + hh * C;
        const float* as = att_s + hh * C;
        const float* ad = att_d + hh * C;
        float ss = 0.f, dd = 0.f;
        for (int c = 0; c < C; c++) {
            float v = hp[c];
            ss = fmaf(v, as[c], ss);
            dd = fmaf(v, ad[c], dd);
        }
        g_asrc[i] = ss;
        g_adst[i] = dd;
        s = ss; d = dd;
    }
    rs[tid] = s; rd[tid] = d;
    __syncthreads();
    #pragma unroll
    for (int o = 128; o >= H; o >>= 1) {
        if (tid < o) {
            rs[tid] = fmaxf(rs[tid], rs[tid + o]);
            rd[tid] = fmaxf(rd[tid], rd[tid + o]);
        }
        __syncthreads();
    }
    if (tid < H) {
        atomicMaxF(&g_gmax[layer][tid], rs[tid]);
        atomicMaxF(&g_gmax[layer][8 + tid], rd[tid]);
    }
}

// ===========================================================================
// Fused softmax+aggregation, 8 heads x 32 ch, warp per dst node, 2 passes:
// pass A: e -> exp(e - global_bound) -> g_e, per-head sum
// pass B: gather-aggregate (R6-proven), scale by 1/sum at the end
// ===========================================================================
__global__ void __launch_bounds__(256) gat_fused8_k(const float* __restrict__ bias,
                                                    int relu, int layer)
{
    int w = (blockIdx.x * blockDim.x + threadIdx.x) >> 5;
    int lane = threadIdx.x & 31;
    if (w >= NN) return;
    int d = w;
    int beg = g_rows[d], end = g_rows[d + 1];

    float adl = (lane < 8) ? g_adst[d * 8 + lane] : 0.f;
    float ad[8], bnd[8];
    #pragma unroll
    for (int h = 0; h < 8; h++) {
        ad[h] = __shfl_sync(0xffffffffu, adl, h);
        float b = g_gmax[layer][h] + g_gmax[layer][8 + h];
        bnd[h] = b > 0.f ? b : 0.2f * b;
    }

    // pass A: exp(e - bnd) stored to g_e, per-head sum
    float sm[8];
    #pragma unroll
    for (int h = 0; h < 8; h++) sm[h] = 0.f;
    for (int p = beg + lane; p < end; p += 32) {
        int s = __ldg(&g_colsrc[p]);
        const float4* ap = (const float4*)(g_asrc + s * 8);
        float4 a0 = __ldg(ap), a1 = __ldg(ap + 1);
        float e[8] = {a0.x + ad[0], a0.y + ad[1], a0.z + ad[2], a0.w + ad[3],
                      a1.x + ad[4], a1.y + ad[5], a1.z + ad[6], a1.w + ad[7]};
        float ex[8];
        #pragma unroll
        for (int h = 0; h < 8; h++) {
            float v = e[h] > 0.f ? e[h] : 0.2f * e[h];
            ex[h] = __expf(v - bnd[h]);
            sm[h] += ex[h];
        }
        float4* ep = (float4*)(g_e + (size_t)p * 8);
        ep[0] = make_float4(ex[0], ex[1], ex[2], ex[3]);
        ep[1] = make_float4(ex[4], ex[5], ex[6], ex[7]);
    }
    #pragma unroll
    for (int h = 0; h < 8; h++)
        #pragma unroll
        for (int o = 16; o; o >>= 1)
            sm[h] += __shfl_xor_sync(0xffffffffu, sm[h], o);

    float inv[8];
    #pragma unroll
    for (int h = 0; h < 8; h++) inv[h] = 1.f / (sm[h] + 1e-16f);

    // pass B: aggregate, unrolled x2 for gather MLP
    float acc[8];
    #pragma unroll
    for (int h = 0; h < 8; h++) acc[h] = 0.f;
    int p = beg;
    for (; p + 1 < end; p += 2) {
        int s0 = __ldg(&g_colsrc[p]);
        int s1 = __ldg(&g_colsrc[p + 1]);
        const float4* ep0 = (const float4*)(g_e + (size_t)p * 8);
        const float4* ep1 = (const float4*)(g_e + (size_t)(p + 1) * 8);
        float4 ea0 = __ldg(ep0), ea1 = __ldg(ep0 + 1);
        float4 eb0 = __ldg(ep1), eb1 = __ldg(ep1 + 1);
        const float* hp0 = g_h + (size_t)s0 * F1;
        const float* hp1 = g_h + (size_t)s1 * F1;
        float w0[8] = {ea0.x, ea0.y, ea0.z, ea0.w, ea1.x, ea1.y, ea1.z, ea1.w};
        float w1[8] = {eb0.x, eb0.y, eb0.z, eb0.w, eb1.x, eb1.y, eb1.z, eb1.w};
        #pragma unroll
        for (int h = 0; h < 8; h++) {
            acc[h] = fmaf(w0[h], __ldg(&hp0[h * 32 + lane]), acc[h]);
            acc[h] = fmaf(w1[h], __ldg(&hp1[h * 32 + lane]), acc[h]);
        }
    }
    if (p < end) {
        int s0 = __ldg(&g_colsrc[p]);
        const float4* ep0 = (const float4*)(g_e + (size_t)p * 8);
        float4 ea0 = __ldg(ep0), ea1 = __ldg(ep0 + 1);
        const float* hp0 = g_h + (size_t)s0 * F1;
        float w0[8] = {ea0.x, ea0.y, ea0.z, ea0.w, ea1.x, ea1.y, ea1.z, ea1.w};
        #pragma unroll
        for (int h = 0; h < 8; h++)
            acc[h] = fmaf(w0[h], __ldg(&hp0[h * 32 + lane]), acc[h]);
    }

    float* op = g_out + (size_t)d * F1;
    #pragma unroll
    for (int h = 0; h < 8; h++) {
        float v = acc[h] * inv[h] + bias[h * 32 + lane];
        if (relu) v = fmaxf(v, 0.f);
        op[h * 32 + lane] = v;
    }
}

// ===========================================================================
// Fused layer-3: 1 head x 40 ch + bias + log_softmax, 2 passes
// ===========================================================================
__global__ void __launch_bounds__(256) gat_fused1_k(const float* __restrict__ bias,
                                                    float* __restrict__ out, int layer)
{
    int w = (blockIdx.x * blockDim.x + threadIdx.x) >> 5;
    int lane = threadIdx.x & 31;
    if (w >= NN) return;
    int d = w;
    int beg = g_rows[d], end = g_rows[d + 1];
    float add = g_adst[d];
    float b = g_gmax[layer][0] + g_gmax[layer][8];
    float bnd = b > 0.f ? b : 0.2f * b;

    // pass A: exp + sum
    float sm = 0.f;
    for (int p = beg + lane; p < end; p += 32) {
        int s = __ldg(&g_colsrc[p]);
        float e = __ldg(&g_asrc[s]) + add;
        e = e > 0.f ? e : 0.2f * e;
        float ex = __expf(e - bnd);
        g_e[p] = ex;
        sm += ex;
    }
    #pragma unroll
    for (int o = 16; o; o >>= 1) sm += __shfl_xor_sync(0xffffffffu, sm, o);
    float inv = 1.f / (sm + 1e-16f);

    // pass B: aggregate, unrolled x2
    float a0 = 0.f, a1 = 0.f;
    int p = beg;
    for (; p + 1 < end; p += 2) {
        int s0 = __ldg(&g_colsrc[p]);
        int s1 = __ldg(&g_colsrc[p + 1]);
        float al0 = __ldg(&g_e[p]);
        float al1 = __ldg(&g_e[p + 1]);
        const float* hp0 = g_h + (size_t)s0 * OUTC;
        const float* hp1 = g_h + (size_t)s1 * OUTC;
        a0 = fmaf(al0, __ldg(&hp0[lane]), a0);
        a0 = fmaf(al1, __ldg(&hp1[lane]), a0);
        if (lane < 8) {
            a1 = fmaf(al0, __ldg(&hp0[lane + 32]), a1);
            a1 = fmaf(al1, __ldg(&hp1[lane + 32]), a1);
        }
    }
    if (p < end) {
        int s0 = __ldg(&g_colsrc[p]);
        float al0 = __ldg(&g_e[p]);
        const float* hp0 = g_h + (size_t)s0 * OUTC;
        a0 = fmaf(al0, __ldg(&hp0[lane]), a0);
        if (lane < 8) a1 = fmaf(al0, __ldg(&hp0[lane + 32]), a1);
    }

    float v0 = a0 * inv + bias[lane];
    float v1 = (lane < 8) ? a1 * inv + bias[lane + 32] : -INFINITY;
    float m = fmaxf(v0, v1);
    #pragma unroll
    for (int o = 16; o; o >>= 1) m = fmaxf(m, __shfl_xor_sync(0xffffffffu, m, o));
    float s2 = __expf(v0 - m) + ((lane < 8) ? __expf(v1 - m) : 0.f);
    #pragma unroll
    for (int o = 16; o; o >>= 1) s2 += __shfl_xor_sync(0xffffffffu, s2, o);
    float lg = m + logf(s2);
    out[(size_t)d * OUTC + lane] = v0 - lg;
    if (lane < 8) out[(size_t)d * OUTC + lane + 32] = v1 - lg;
}

// ===========================================================================
// TF32 tensor-core GEMM with cp.async 2-stage double buffering.
// ===========================================================================
#define GBM 128
#define GBN 64
#define GBK 16
#define AS_STRIDE 20   // 16 + 4 pad
#define BS_STRIDE 72   // 64 + 8 pad

__device__ __forceinline__ void cp16(uint32_t dst, const void* src, int valid)
{
    asm volatile("cp.async.ca.shared.global [%0], [%1], 16, %2;\n"
                 :: "r"(dst), "l"(src), "r"(valid ? 16 : 0));
}

__device__ __forceinline__ void mma1688(float* c, const uint32_t* a, const uint32_t* b)
{
    asm volatile(
        "mma.sync.aligned.m16n8k8.row.col.f32.tf32.tf32.f32 "
        "{%0,%1,%2,%3},{%4,%5,%6,%7},{%8,%9},{%0,%1,%2,%3};"
        : "+f"(c[0]), "+f"(c[1]), "+f"(c[2]), "+f"(c[3])
        : "r"(a[0]), "r"(a[1]), "r"(a[2]), "r"(a[3]), "r"(b[0]), "r"(b[1]));
}

__global__ void __launch_bounds__(256) tf32gemm_k(const float* __restrict__ Aext,
                                                  const float* __restrict__ B,
                                                  int M, int Ncol, int K, int a_internal)
{
    const float* A = a_internal ? g_out : Aext;
    __shared__ float As[2][GBM * AS_STRIDE];
    __shared__ float Bs[2][GBK * BS_STRIDE];

    int tid  = threadIdx.x;
    int warp = tid >> 5;
    int lane = tid & 31;
    int wm = warp >> 1;
    int wn = warp & 1;
    int bm = blockIdx.y * GBM;
    int bn = blockIdx.x * GBN;
    int lr = lane >> 2;
    int lc = lane & 3;

    int ar0 = tid >> 2;
    int ac  = (tid & 3) * 4;
    int br  = tid >> 4;
    int bc  = (tid & 15) * 4;

    uint32_t as_base = (uint32_t)__cvta_generic_to_shared(&As[0][0]);
    uint32_t bs_base = (uint32_t)__cvta_generic_to_shared(&Bs[0][0]);
    const uint32_t AS_BYTES = GBM * AS_STRIDE * 4;
    const uint32_t BS_BYTES = GBK * BS_STRIDE * 4;

    int niter = K / GBK;

    {
        int k0 = 0;
        #pragma unroll
        for (int i = 0; i < 2; i++) {
            int r = ar0 + i * 64;
            int gr = bm + r;
            int ok = gr < M;
            const float* src = A + (size_t)(ok ? gr : 0) * K + k0 + ac;
            cp16(as_base + (r * AS_STRIDE + ac) * 4, src, ok);
        }
        {
            int gc = bn + bc;
            int ok = gc < Ncol;
            const float* src = B + (size_t)(k0 + br) * Ncol + (ok ? gc : 0);
            cp16(bs_base + (br * BS_STRIDE + bc) * 4, src, ok);
        }
        asm volatile("cp.async.commit_group;\n" ::);
    }

    float c[2][4][4];
    #pragma unroll
    for (int i = 0; i < 2; i++)
        #pragma unroll
        for (int j = 0; j < 4; j++)
            #pragma unroll
            for (int r = 0; r < 4; r++) c[i][j][r] = 0.f;

    int buf = 0;
    for (int it = 0; it < niter; it++) {
        int has_next = (it + 1 < niter);
        if (has_next) {
            int k0 = (it + 1) * GBK;
            uint32_t ab = as_base + (buf ^ 1) * AS_BYTES;
            uint32_t bb = bs_base + (buf ^ 1) * BS_BYTES;
            #pragma unroll
            for (int i = 0; i < 2; i++) {
                int r = ar0 + i * 64;
                int gr = bm + r;
                int ok = gr < M;
                const float* src = A + (size_t)(ok ? gr : 0) * K + k0 + ac;
                cp16(ab + (r * AS_STRIDE + ac) * 4, src, ok);
            }
            {
                int gc = bn + bc;
                int ok = gc < Ncol;
                const float* src = B + (size_t)(k0 + br) * Ncol + (ok ? gc : 0);
                cp16(bb + (br * BS_STRIDE + bc) * 4, src, ok);
            }
            asm volatile("cp.async.commit_group;\n" ::);
            asm volatile("cp.async.wait_group 1;\n" ::);
        } else {
            asm volatile("cp.async.wait_group 0;\n" ::);
        }
        __syncthreads();

        const float* Asb = As[buf];
        const float* Bsb = Bs[buf];
        #pragma unroll
        for (int kk = 0; kk < GBK; kk += 8) {
            uint32_t afrag[2][4], bfrag[4][2];
            #pragma unroll
            for (int i = 0; i < 2; i++) {
                int rb = wm * 32 + i * 16;
                afrag[i][0] = __float_as_uint(Asb[(rb + lr)     * AS_STRIDE + kk + lc]);
                afrag[i][1] = __float_as_uint(Asb[(rb + 8 + lr) * AS_STRIDE + kk + lc]);
                afrag[i][2] = __float_as_uint(Asb[(rb + lr)     * AS_STRIDE + kk + 4 + lc]);
                afrag[i][3] = __float_as_uint(Asb[(rb + 8 + lr) * AS_STRIDE + kk + 4 + lc]);
            }
            #pragma unroll
            for (int j = 0; j < 4; j++) {
                int nb = wn * 32 + j * 8;
                bfrag[j][0] = __float_as_uint(Bsb[(kk + lc)     * BS_STRIDE + nb + lr]);
                bfrag[j][1] = __float_as_uint(Bsb[(kk + 4 + lc) * BS_STRIDE + nb + lr]);
            }
            #pragma unroll
            for (int i = 0; i < 2; i++)
                #pragma unroll
                for (int j = 0; j < 4; j++)
                    mma1688(c[i][j], afrag[i], bfrag[j]);
        }
        __syncthreads();
        buf ^= 1;
    }

    #pragma unroll
    for (int i = 0; i < 2; i++) {
        int r0 = bm + wm * 32 + i * 16 + lr;
        #pragma unroll
        for (int j = 0; j < 4; j++) {
            int col = bn + wn * 32 + j * 8 + lc * 2;
            if (col < Ncol) {
                if (r0 < M) {
                    g_h[(size_t)r0 * Ncol + col]     = c[i][j][0];
                    g_h[(size_t)r0 * Ncol + col + 1] = c[i][j][1];
                }
                if (r0 + 8 < M) {
                    g_h[(size_t)(r0 + 8) * Ncol + col]     = c[i][j][2];
                    g_h[(size_t)(r0 + 8) * Ncol + col + 1] = c[i][j][3];
                }
            }
        }
    }
}

// ===========================================================================
// Launcher
// ===========================================================================
extern "C" void kernel_launch(void* const* d_in, const int* in_sizes, int n_in,
                              void* d_out, int out_size)
{
    const float* x    = (const float*)d_in[0];
    const int*   ei   = (const int*)  d_in[1];
    const int*   srcv = ei;
    const int*   dstv = ei + EE;
    const float* W1  = (const float*)d_in[2];
    const float* as1 = (const float*)d_in[3];
    const float* ad1 = (const float*)d_in[4];
    const float* b1  = (const float*)d_in[5];
    const float* W2  = (const float*)d_in[6];
    const float* as2 = (const float*)d_in[7];
    const float* ad2 = (const float*)d_in[8];
    const float* b2  = (const float*)d_in[9];
    const float* W3  = (const float*)d_in[10];
    const float* as3 = (const float*)d_in[11];
    const float* ad3 = (const float*)d_in[12];
    const float* b3  = (const float*)d_in[13];
    float* out = (float*)d_out;

    dim3 blk(256);
    dim3 gemm_g1((F1 + GBN - 1) / GBN,   (NN + GBM - 1) / GBM);
    dim3 gemm_g3((OUTC + GBN - 1) / GBN, (NN + GBM - 1) / GBM);
    int nbN    = (NN + 255) / 256;
    int nbE    = (EE + 255) / 256;
    int nbE2   = (E2V + 255) / 256;
    int nbNH   = (NN * 8 + 255) / 256;
    int nbWarp = (NN * 32 + 255) / 256;

    // ---- CSR build (also resets g_gmax) ----
    init_deg_k<<<nbN, blk>>>();
    count_k<<<nbE, blk>>>(dstv);
    scan1_k<<<NBLK, SB>>>();
    scan2_k<<<1, 128>>>();
    scan3_k<<<nbN, blk>>>();
    scatter_k<<<nbE2, blk>>>(srcv, dstv);

    // ---- layer 1: 128 -> 8x32 ----
    tf32gemm_k<<<gemm_g1, blk>>>(x, W1, NN, F1, 128, 0);
    dots_k<8><<<nbNH, blk>>>(as1, ad1, 32, 0);
    gat_fused8_k<<<nbWarp, blk>>>(b1, 1, 0);

    // ---- layer 2: 256 -> 8x32 ----
    tf32gemm_k<<<gemm_g1, blk>>>(nullptr, W2, NN, F1, F1, 1);
    dots_k<8><<<nbNH, blk>>>(as2, ad2, 32, 1);
    gat_fused8_k<<<nbWarp, blk>>>(b2, 1, 1);

    // ---- layer 3: 256 -> 40 + log_softmax ----
    tf32gemm_k<<<gemm_g3, blk>>>(nullptr, W3, NN, OUTC, F1, 1);
    dots_k<1><<<nbN, blk>>>(as3, ad3, OUTC, 2);
    gat_fused1_k<<<nbWarp, blk>>>(b3, out, 2);
}

// round 9
// speedup vs baseline: 1.1640x; 1.0728x over previous
#include <cuda_runtime.h>
#include <math.h>
#include <stdint.h>

#define NN   50000
#define EE   800000
#define E2V  (EE + NN)
#define F1   256
#define OUTC 40
#define SB   512
#define NBLK ((NN + SB - 1) / SB)

// ---- scratch ----
__device__ float g_h   [(size_t)NN * F1];
__device__ float g_out [(size_t)NN * F1];
__device__ float g_asrc[NN * 8];
__device__ float g_adst[NN * 8];
__device__ int   g_deg [NN];
__device__ int   g_rows[NN + 1];
__device__ int   g_cur [NN];
__device__ int   g_colsrc[E2V];
__device__ int   g_bsum[NBLK + 1];
__device__ float g_gmax[3][16];   // per layer: [0..7]=max a_src per head, [8..15]=max a_dst

// ===========================================================================
// Float atomic max (order-free, handles mixed signs; init to -inf)
// ===========================================================================
__device__ __forceinline__ void atomicMaxF(float* addr, float val)
{
    unsigned int u = __float_as_uint(val);
    if (u >> 31) atomicMin((unsigned int*)addr, u);
    else         atomicMax((int*)addr, (int)u);
}

// ===========================================================================
// CSR build (dst-grouped): count -> scan -> scatter
// ===========================================================================
__global__ void init_deg_k()
{
    int i = blockIdx.x * blockDim.x + threadIdx.x;
    if (i < NN) g_deg[i] = 1;
    if (i < 48) ((float*)g_gmax)[i] = __int_as_float(0xFF800000);
}

__global__ void count_k(const int* __restrict__ dst)
{
    int e = blockIdx.x * blockDim.x + threadIdx.x;
    if (e < EE) atomicAdd(&g_deg[dst[e]], 1);
}

__global__ void scan1_k()
{
    __shared__ int sh[SB];
    int i = blockIdx.x * SB + threadIdx.x;
    sh[threadIdx.x] = (i < NN) ? g_deg[i] : 0;
    __syncthreads();
    #pragma unroll
    for (int o = 1; o < SB; o <<= 1) {
        int t = (threadIdx.x >= o) ? sh[threadIdx.x - o] : 0;
        __syncthreads();
        sh[threadIdx.x] += t;
        __syncthreads();
    }
    if (i < NN) g_rows[i + 1] = sh[threadIdx.x];
    if (threadIdx.x == SB - 1) g_bsum[blockIdx.x] = sh[SB - 1];
}

__global__ void scan2_k()
{
    __shared__ int sh[128];
    int t = threadIdx.x;
    int v = (t < NBLK) ? g_bsum[t] : 0;
    sh[t] = v;
    __syncthreads();
    #pragma unroll
    for (int o = 1; o < 128; o <<= 1) {
        int u = (t >= o) ? sh[t - o] : 0;
        __syncthreads();
        sh[t] += u;
        __syncthreads();
    }
    if (t < NBLK) g_bsum[t] = sh[t] - v;   // exclusive
}

__global__ void scan3_k()
{
    int i = blockIdx.x * blockDim.x + threadIdx.x;
    if (i >= NN) return;
    int end = g_rows[i + 1] + g_bsum[i / SB];
    g_rows[i + 1] = end;
    g_cur[i] = end - g_deg[i];
    if (i == 0) g_rows[0] = 0;
}

__global__ void scatter_k(const int* __restrict__ src, const int* __restrict__ dst)
{
    int e = blockIdx.x * blockDim.x + threadIdx.x;
    if (e >= E2V) return;
    int s, d;
    if (e < EE) { s = src[e]; d = dst[e]; } else { s = d = e - EE; }
    int pos = atomicAdd(&g_cur[d], 1);
    g_colsrc[pos] = s;
}

// ===========================================================================
// Attention dot products + per-head global max (block reduce + atomicMax)
// ===========================================================================
template<int H>
__global__ void __launch_bounds__(256) dots_k(const float* __restrict__ att_s,
                                              const float* __restrict__ att_d,
                                              int C, int layer)
{
    __shared__ float rs[256], rd[256];
    int tid = threadIdx.x;
    int i = blockIdx.x * blockDim.x + tid;
    float s = -INFINITY, d = -INFINITY;
    if (i < NN * H) {
        int n = i / H, hh = i % H;
        const float* hp = g_h + (size_t)n * H * C + hh * C;
        const float* as = att_s + hh * C;
        const float* ad = att_d + hh * C;
        float ss = 0.f, dd = 0.f;
        for (int c = 0; c < C; c++) {
            float v = hp[c];
            ss = fmaf(v, as[c], ss);
            dd = fmaf(v, ad[c], dd);
        }
        g_asrc[i] = ss;
        g_adst[i] = dd;
        s = ss; d = dd;
    }
    rs[tid] = s; rd[tid] = d;
    __syncthreads();
    #pragma unroll
    for (int o = 128; o >= H; o >>= 1) {
        if (tid < o) {
            rs[tid] = fmaxf(rs[tid], rs[tid + o]);
            rd[tid] = fmaxf(rd[tid], rd[tid + o]);
        }
        __syncthreads();
    }
    if (tid < H) {
        atomicMaxF(&g_gmax[layer][tid], rs[tid]);
        atomicMaxF(&g_gmax[layer][8 + tid], rd[tid]);
    }
}

// ===========================================================================
// SINGLE-PASS fused softmax + aggregation, 8 heads x 32 ch, warp per node.
// 4-edge chunks: lane = (edge-slot 0-3) x (head 0-7) computes exp for its
// (edge, head); staged via SMEM; aggregation reads weights with broadcast
// LDS.128. Normalization deferred via global per-head bound (no max pass).
// ===========================================================================
__global__ void __launch_bounds__(256) gat_fused8_k(const float* __restrict__ bias,
                                                    int relu, int layer)
{
    __shared__ float sex[8][32];
    __shared__ int   ssrc[8][4];

    int w = (blockIdx.x * blockDim.x + threadIdx.x) >> 5;
    int lane = threadIdx.x & 31;
    int wl = (threadIdx.x >> 5);
    if (w >= NN) return;
    int d = w;
    int beg = g_rows[d], end = g_rows[d + 1];

    int hsel  = lane & 7;    // head this lane computes exp for
    int eslot = lane >> 3;   // edge slot within chunk (0-3)

    float adh = __ldg(&g_adst[d * 8 + hsel]);
    float bh  = g_gmax[layer][hsel] + g_gmax[layer][8 + hsel];
    float bndh = bh > 0.f ? bh : 0.2f * bh;

    float acc[8];
    #pragma unroll
    for (int h = 0; h < 8; h++) acc[h] = 0.f;
    float smpart = 0.f;   // partial sum for head hsel over this lane's edge slots

    int p0 = beg;
    int nfull = (end - beg) >> 2;
    for (int ch = 0; ch < nfull; ch++, p0 += 4) {
        int s = __ldg(&g_colsrc[p0 + eslot]);
        float e = __ldg(&g_asrc[s * 8 + hsel]) + adh;
        e = e > 0.f ? e : 0.2f * e;
        float ex = __expf(e - bndh);
        smpart += ex;
        sex[wl][lane] = ex;
        if (hsel == 0) ssrc[wl][eslot] = s;
        __syncwarp();
        #pragma unroll
        for (int e4 = 0; e4 < 4; e4++) {
            int se = ssrc[wl][e4];
            float4 w0 = *(const float4*)&sex[wl][e4 * 8];
            float4 w1 = *(const float4*)&sex[wl][e4 * 8 + 4];
            const float* hp = g_h + (size_t)se * F1;
            acc[0] = fmaf(w0.x, __ldg(&hp[  0 + lane]), acc[0]);
            acc[1] = fmaf(w0.y, __ldg(&hp[ 32 + lane]), acc[1]);
            acc[2] = fmaf(w0.z, __ldg(&hp[ 64 + lane]), acc[2]);
            acc[3] = fmaf(w0.w, __ldg(&hp[ 96 + lane]), acc[3]);
            acc[4] = fmaf(w1.x, __ldg(&hp[128 + lane]), acc[4]);
            acc[5] = fmaf(w1.y, __ldg(&hp[160 + lane]), acc[5]);
            acc[6] = fmaf(w1.z, __ldg(&hp[192 + lane]), acc[6]);
            acc[7] = fmaf(w1.w, __ldg(&hp[224 + lane]), acc[7]);
        }
        __syncwarp();
    }
    int rem = end - p0;
    if (rem > 0) {
        float ex = 0.f;
        int s = 0;
        if (eslot < rem) {
            s = __ldg(&g_colsrc[p0 + eslot]);
            float e = __ldg(&g_asrc[s * 8 + hsel]) + adh;
            e = e > 0.f ? e : 0.2f * e;
            ex = __expf(e - bndh);
            smpart += ex;
        }
        sex[wl][lane] = ex;
        if (hsel == 0 && eslot < rem) ssrc[wl][eslot] = s;
        __syncwarp();
        for (int e4 = 0; e4 < rem; e4++) {
            int se = ssrc[wl][e4];
            float4 w0 = *(const float4*)&sex[wl][e4 * 8];
            float4 w1 = *(const float4*)&sex[wl][e4 * 8 + 4];
            const float* hp = g_h + (size_t)se * F1;
            acc[0] = fmaf(w0.x, __ldg(&hp[  0 + lane]), acc[0]);
            acc[1] = fmaf(w0.y, __ldg(&hp[ 32 + lane]), acc[1]);
            acc[2] = fmaf(w0.z, __ldg(&hp[ 64 + lane]), acc[2]);
            acc[3] = fmaf(w0.w, __ldg(&hp[ 96 + lane]), acc[3]);
            acc[4] = fmaf(w1.x, __ldg(&hp[128 + lane]), acc[4]);
            acc[5] = fmaf(w1.y, __ldg(&hp[160 + lane]), acc[5]);
            acc[6] = fmaf(w1.z, __ldg(&hp[192 + lane]), acc[6]);
            acc[7] = fmaf(w1.w, __ldg(&hp[224 + lane]), acc[7]);
        }
        __syncwarp();
    }

    // complete per-head sums: lanes {h, h+8, h+16, h+24} hold partials of head h
    smpart += __shfl_xor_sync(0xffffffffu, smpart, 8);
    smpart += __shfl_xor_sync(0xffffffffu, smpart, 16);
    float invl = 1.f / (smpart + 1e-16f);   // every lane: inv for head (lane&7)

    float* op = g_out + (size_t)d * F1;
    #pragma unroll
    for (int h = 0; h < 8; h++) {
        float inv = __shfl_sync(0xffffffffu, invl, h);
        float v = acc[h] * inv + bias[h * 32 + lane];
        if (relu) v = fmaxf(v, 0.f);
        op[h * 32 + lane] = v;
    }
}

// ===========================================================================
// SINGLE-PASS fused layer-3: 1 head x 40 ch + bias + log_softmax.
// 32-edge chunks; exp staged via SMEM; no edge scratch buffer.
// ===========================================================================
__global__ void __launch_bounds__(256) gat_fused1_k(const float* __restrict__ bias,
                                                    float* __restrict__ out, int layer)
{
    __shared__ float sex[8][32];
    __shared__ int   ssrc[8][32];

    int w = (blockIdx.x * blockDim.x + threadIdx.x) >> 5;
    int lane = threadIdx.x & 31;
    int wl = (threadIdx.x >> 5);
    if (w >= NN) return;
    int d = w;
    int beg = g_rows[d], end = g_rows[d + 1];
    float add = g_adst[d];
    float b = g_gmax[layer][0] + g_gmax[layer][8];
    float bnd = b > 0.f ? b : 0.2f * b;

    float a0 = 0.f, a1 = 0.f, smpart = 0.f;

    for (int p0 = beg; p0 < end; p0 += 32) {
        int ne = min(32, end - p0);
        float ex = 0.f;
        int s = 0;
        if (lane < ne) {
            s = __ldg(&g_colsrc[p0 + lane]);
            float e = __ldg(&g_asrc[s]) + add;
            e = e > 0.f ? e : 0.2f * e;
            ex = __expf(e - bnd);
            smpart += ex;
        }
        sex[wl][lane] = ex;
        ssrc[wl][lane] = s;
        __syncwarp();
        for (int e = 0; e < ne; e++) {
            int se = ssrc[wl][e];
            float al = sex[wl][e];
            const float* hp = g_h + (size_t)se * OUTC;
            a0 = fmaf(al, __ldg(&hp[lane]), a0);
            if (lane < 8) a1 = fmaf(al, __ldg(&hp[lane + 32]), a1);
        }
        __syncwarp();
    }
    #pragma unroll
    for (int o = 16; o; o >>= 1) smpart += __shfl_xor_sync(0xffffffffu, smpart, o);
    float inv = 1.f / (smpart + 1e-16f);

    float v0 = a0 * inv + bias[lane];
    float v1 = (lane < 8) ? a1 * inv + bias[lane + 32] : -INFINITY;
    float m = fmaxf(v0, v1);
    #pragma unroll
    for (int o = 16; o; o >>= 1) m = fmaxf(m, __shfl_xor_sync(0xffffffffu, m, o));
    float s2 = __expf(v0 - m) + ((lane < 8) ? __expf(v1 - m) : 0.f);
    #pragma unroll
    for (int o = 16; o; o >>= 1) s2 += __shfl_xor_sync(0xffffffffu, s2, o);
    float lg = m + logf(s2);
    out[(size_t)d * OUTC + lane] = v0 - lg;
    if (lane < 8) out[(size_t)d * OUTC + lane + 32] = v1 - lg;
}

// ===========================================================================
// TF32 tensor-core GEMM with cp.async 2-stage double buffering (unchanged).
// ===========================================================================
#define GBM 128
#define GBN 64
#define GBK 16
#define AS_STRIDE 20   // 16 + 4 pad
#define BS_STRIDE 72   // 64 + 8 pad

__device__ __forceinline__ void cp16(uint32_t dst, const void* src, int valid)
{
    asm volatile("cp.async.ca.shared.global [%0], [%1], 16, %2;\n"
                 :: "r"(dst), "l"(src), "r"(valid ? 16 : 0));
}

__device__ __forceinline__ void mma1688(float* c, const uint32_t* a, const uint32_t* b)
{
    asm volatile(
        "mma.sync.aligned.m16n8k8.row.col.f32.tf32.tf32.f32 "
        "{%0,%1,%2,%3},{%4,%5,%6,%7},{%8,%9},{%0,%1,%2,%3};"
        : "+f"(c[0]), "+f"(c[1]), "+f"(c[2]), "+f"(c[3])
        : "r"(a[0]), "r"(a[1]), "r"(a[2]), "r"(a[3]), "r"(b[0]), "r"(b[1]));
}

__global__ void __launch_bounds__(256) tf32gemm_k(const float* __restrict__ Aext,
                                                  const float* __restrict__ B,
                                                  int M, int Ncol, int K, int a_internal)
{
    const float* A = a_internal ? g_out : Aext;
    __shared__ float As[2][GBM * AS_STRIDE];
    __shared__ float Bs[2][GBK * BS_STRIDE];

    int tid  = threadIdx.x;
    int warp = tid >> 5;
    int lane = tid & 31;
    int wm = warp >> 1;
    int wn = warp & 1;
    int bm = blockIdx.y * GBM;
    int bn = blockIdx.x * GBN;
    int lr = lane >> 2;
    int lc = lane & 3;

    int ar0 = tid >> 2;
    int ac  = (tid & 3) * 4;
    int br  = tid >> 4;
    int bc  = (tid & 15) * 4;

    uint32_t as_base = (uint32_t)__cvta_generic_to_shared(&As[0][0]);
    uint32_t bs_base = (uint32_t)__cvta_generic_to_shared(&Bs[0][0]);
    const uint32_t AS_BYTES = GBM * AS_STRIDE * 4;
    const uint32_t BS_BYTES = GBK * BS_STRIDE * 4;

    int niter = K / GBK;

    {
        int k0 = 0;
        #pragma unroll
        for (int i = 0; i < 2; i++) {
            int r = ar0 + i * 64;
            int gr = bm + r;
            int ok = gr < M;
            const float* src = A + (size_t)(ok ? gr : 0) * K + k0 + ac;
            cp16(as_base + (r * AS_STRIDE + ac) * 4, src, ok);
        }
        {
            int gc = bn + bc;
            int ok = gc < Ncol;
            const float* src = B + (size_t)(k0 + br) * Ncol + (ok ? gc : 0);
            cp16(bs_base + (br * BS_STRIDE + bc) * 4, src, ok);
        }
        asm volatile("cp.async.commit_group;\n" ::);
    }

    float c[2][4][4];
    #pragma unroll
    for (int i = 0; i < 2; i++)
        #pragma unroll
        for (int j = 0; j < 4; j++)
            #pragma unroll
            for (int r = 0; r < 4; r++) c[i][j][r] = 0.f;

    int buf = 0;
    for (int it = 0; it < niter; it++) {
        int has_next = (it + 1 < niter);
        if (has_next) {
            int k0 = (it + 1) * GBK;
            uint32_t ab = as_base + (buf ^ 1) * AS_BYTES;
            uint32_t bb = bs_base + (buf ^ 1) * BS_BYTES;
            #pragma unroll
            for (int i = 0; i < 2; i++) {
                int r = ar0 + i * 64;
                int gr = bm + r;
                int ok = gr < M;
                const float* src = A + (size_t)(ok ? gr : 0) * K + k0 + ac;
                cp16(ab + (r * AS_STRIDE + ac) * 4, src, ok);
            }
            {
                int gc = bn + bc;
                int ok = gc < Ncol;
                const float* src = B + (size_t)(k0 + br) * Ncol + (ok ? gc : 0);
                cp16(bb + (br * BS_STRIDE + bc) * 4, src, ok);
            }
            asm volatile("cp.async.commit_group;\n" ::);
            asm volatile("cp.async.wait_group 1;\n" ::);
        } else {
            asm volatile("cp.async.wait_group 0;\n" ::);
        }
        __syncthreads();

        const float* Asb = As[buf];
        const float* Bsb = Bs[buf];
        #pragma unroll
        for (int kk = 0; kk < GBK; kk += 8) {
            uint32_t afrag[2][4], bfrag[4][2];
            #pragma unroll
            for (int i = 0; i < 2; i++) {
                int rb = wm * 32 + i * 16;
                afrag[i][0] = __float_as_uint(Asb[(rb + lr)     * AS_STRIDE + kk + lc]);
                afrag[i][1] = __float_as_uint(Asb[(rb + 8 + lr) * AS_STRIDE + kk + lc]);
                afrag[i][2] = __float_as_uint(Asb[(rb + lr)     * AS_STRIDE + kk + 4 + lc]);
                afrag[i][3] = __float_as_uint(Asb[(rb + 8 + lr) * AS_STRIDE + kk + 4 + lc]);
            }
            #pragma unroll
            for (int j = 0; j < 4; j++) {
                int nb = wn * 32 + j * 8;
                bfrag[j][0] = __float_as_uint(Bsb[(kk + lc)     * BS_STRIDE + nb + lr]);
                bfrag[j][1] = __float_as_uint(Bsb[(kk + 4 + lc) * BS_STRIDE + nb + lr]);
            }
            #pragma unroll
            for (int i = 0; i < 2; i++)
                #pragma unroll
                for (int j = 0; j < 4; j++)
                    mma1688(c[i][j], afrag[i], bfrag[j]);
        }
        __syncthreads();
        buf ^= 1;
    }

    #pragma unroll
    for (int i = 0; i < 2; i++) {
        int r0 = bm + wm * 32 + i * 16 + lr;
        #pragma unroll
        for (int j = 0; j < 4; j++) {
            int col = bn + wn * 32 + j * 8 + lc * 2;
            if (col < Ncol) {
                if (r0 < M) {
                    g_h[(size_t)r0 * Ncol + col]     = c[i][j][0];
                    g_h[(size_t)r0 * Ncol + col + 1] = c[i][j][1];
                }
                if (r0 + 8 < M) {
                    g_h[(size_t)(r0 + 8) * Ncol + col]     = c[i][j][2];
                    g_h[(size_t)(r0 + 8) * Ncol + col + 1] = c[i][j][3];
                }
            }
        }
    }
}

// ===========================================================================
// Launcher
// ===========================================================================
extern "C" void kernel_launch(void* const* d_in, const int* in_sizes, int n_in,
                              void* d_out, int out_size)
{
    const float* x    = (const float*)d_in[0];
    const int*   ei   = (const int*)  d_in[1];
    const int*   srcv = ei;
    const int*   dstv = ei + EE;
    const float* W1  = (const float*)d_in[2];
    const float* as1 = (const float*)d_in[3];
    const float* ad1 = (const float*)d_in[4];
    const float* b1  = (const float*)d_in[5];
    const float* W2  = (const float*)d_in[6];
    const float* as2 = (const float*)d_in[7];
    const float* ad2 = (const float*)d_in[8];
    const float* b2  = (const float*)d_in[9];
    const float* W3  = (const float*)d_in[10];
    const float* as3 = (const float*)d_in[11];
    const float* ad3 = (const float*)d_in[12];
    const float* b3  = (const float*)d_in[13];
    float* out = (float*)d_out;

    dim3 blk(256);
    dim3 gemm_g1((F1 + GBN - 1) / GBN,   (NN + GBM - 1) / GBM);
    dim3 gemm_g3((OUTC + GBN - 1) / GBN, (NN + GBM - 1) / GBM);
    int nbN    = (NN + 255) / 256;
    int nbE    = (EE + 255) / 256;
    int nbE2   = (E2V + 255) / 256;
    int nbNH   = (NN * 8 + 255) / 256;
    int nbWarp = (NN * 32 + 255) / 256;

    // ---- CSR build (also resets g_gmax) ----
    init_deg_k<<<nbN, blk>>>();
    count_k<<<nbE, blk>>>(dstv);
    scan1_k<<<NBLK, SB>>>();
    scan2_k<<<1, 128>>>();
    scan3_k<<<nbN, blk>>>();
    scatter_k<<<nbE2, blk>>>(srcv, dstv);

    // ---- layer 1: 128 -> 8x32 ----
    tf32gemm_k<<<gemm_g1, blk>>>(x, W1, NN, F1, 128, 0);
    dots_k<8><<<nbNH, blk>>>(as1, ad1, 32, 0);
    gat_fused8_k<<<nbWarp, blk>>>(b1, 1, 0);

    // ---- layer 2: 256 -> 8x32 ----
    tf32gemm_k<<<gemm_g1, blk>>>(nullptr, W2, NN, F1, F1, 1);
    dots_k<8><<<nbNH, blk>>>(as2, ad2, 32, 1);
    gat_fused8_k<<<nbWarp, blk>>>(b2, 1, 1);

    // ---- layer 3: 256 -> 40 + log_softmax ----
    tf32gemm_k<<<gemm_g3, blk>>>(nullptr, W3, NN, OUTC, F1, 1);
    dots_k<1><<<nbN, blk>>>(as3, ad3, OUTC, 2);
    gat_fused1_k<<<nbWarp, blk>>>(b3, out, 2);
}

// round 10
// speedup vs baseline: 1.6021x; 1.3763x over previous
#include <cuda_runtime.h>
#include <cuda_fp16.h>
#include <math.h>
#include <stdint.h>

#define NN   50000
#define EE   800000
#define E2V  (EE + NN)
#define F1   256
#define OUTC 40
#define SB   512
#define NBLK ((NN + SB - 1) / SB)

// ---- scratch ----
__device__ __half g_h16[(size_t)NN * F1];   // transformed features (fp16)
__device__ float  g_out[(size_t)NN * F1];   // aggregated output / next layer's A (fp32)
__device__ float  g_asrc[NN * 8];
__device__ float  g_adst[NN * 8];
__device__ int    g_deg [NN];
__device__ int    g_rows[NN + 1];
__device__ int    g_cur [NN];
__device__ int    g_colsrc[E2V];
__device__ int    g_bsum[NBLK + 1];
__device__ float  g_gmax[3][16];   // [0..7]=max a_src per head, [8..15]=max a_dst

// ===========================================================================
// Float atomic max (order-free, handles mixed signs; init to -inf)
// ===========================================================================
__device__ __forceinline__ void atomicMaxF(float* addr, float val)
{
    unsigned int u = __float_as_uint(val);
    if (u >> 31) atomicMin((unsigned int*)addr, u);
    else         atomicMax((int*)addr, (int)u);
}

// ===========================================================================
// CSR build (dst-grouped): count -> scan -> scatter
// ===========================================================================
__global__ void init_deg_k()
{
    int i = blockIdx.x * blockDim.x + threadIdx.x;
    if (i < NN) g_deg[i] = 1;
    if (i < 48) ((float*)g_gmax)[i] = __int_as_float(0xFF800000);
}

__global__ void count_k(const int* __restrict__ dst)
{
    int e = blockIdx.x * blockDim.x + threadIdx.x;
    if (e < EE) atomicAdd(&g_deg[dst[e]], 1);
}

__global__ void scan1_k()
{
    __shared__ int sh[SB];
    int i = blockIdx.x * SB + threadIdx.x;
    sh[threadIdx.x] = (i < NN) ? g_deg[i] : 0;
    __syncthreads();
    #pragma unroll
    for (int o = 1; o < SB; o <<= 1) {
        int t = (threadIdx.x >= o) ? sh[threadIdx.x - o] : 0;
        __syncthreads();
        sh[threadIdx.x] += t;
        __syncthreads();
    }
    if (i < NN) g_rows[i + 1] = sh[threadIdx.x];
    if (threadIdx.x == SB - 1) g_bsum[blockIdx.x] = sh[SB - 1];
}

__global__ void scan2_k()
{
    __shared__ int sh[128];
    int t = threadIdx.x;
    int v = (t < NBLK) ? g_bsum[t] : 0;
    sh[t] = v;
    __syncthreads();
    #pragma unroll
    for (int o = 1; o < 128; o <<= 1) {
        int u = (t >= o) ? sh[t - o] : 0;
        __syncthreads();
        sh[t] += u;
        __syncthreads();
    }
    if (t < NBLK) g_bsum[t] = sh[t] - v;   // exclusive
}

__global__ void scan3_k()
{
    int i = blockIdx.x * blockDim.x + threadIdx.x;
    if (i >= NN) return;
    int end = g_rows[i + 1] + g_bsum[i / SB];
    g_rows[i + 1] = end;
    g_cur[i] = end - g_deg[i];
    if (i == 0) g_rows[0] = 0;
}

__global__ void scatter_k(const int* __restrict__ src, const int* __restrict__ dst)
{
    int e = blockIdx.x * blockDim.x + threadIdx.x;
    if (e >= E2V) return;
    int s, d;
    if (e < EE) { s = src[e]; d = dst[e]; } else { s = d = e - EE; }
    int pos = atomicAdd(&g_cur[d], 1);
    g_colsrc[pos] = s;
}

// ===========================================================================
// Attention dot products (fp16 h) + per-head global max
// ===========================================================================
template<int H>
__global__ void __launch_bounds__(256) dots_k(const float* __restrict__ att_s,
                                              const float* __restrict__ att_d,
                                              int C, int layer)
{
    __shared__ float rs[256], rd[256];
    int tid = threadIdx.x;
    int i = blockIdx.x * blockDim.x + tid;
    float s = -INFINITY, d = -INFINITY;
    if (i < NN * H) {
        int n = i / H, hh = i % H;
        const __half2* hp = (const __half2*)(g_h16 + (size_t)n * H * C + hh * C);
        const float* as = att_s + hh * C;
        const float* ad = att_d + hh * C;
        float ss = 0.f, dd = 0.f;
        for (int c = 0; c < C / 2; c++) {
            float2 v = __half22float2(__ldg(&hp[c]));
            ss = fmaf(v.x, as[2 * c], ss);
            ss = fmaf(v.y, as[2 * c + 1], ss);
            dd = fmaf(v.x, ad[2 * c], dd);
            dd = fmaf(v.y, ad[2 * c + 1], dd);
        }
        g_asrc[i] = ss;
        g_adst[i] = dd;
        s = ss; d = dd;
    }
    rs[tid] = s; rd[tid] = d;
    __syncthreads();
    #pragma unroll
    for (int o = 128; o >= H; o >>= 1) {
        if (tid < o) {
            rs[tid] = fmaxf(rs[tid], rs[tid + o]);
            rd[tid] = fmaxf(rd[tid], rd[tid + o]);
        }
        __syncthreads();
    }
    if (tid < H) {
        atomicMaxF(&g_gmax[layer][tid], rs[tid]);
        atomicMaxF(&g_gmax[layer][8 + tid], rd[tid]);
    }
}

// ===========================================================================
// SINGLE-PASS fused softmax + aggregation, fp16 h gathers.
// 4-edge chunks; lane = (edge-slot 0-3) x (head 0-7) computes exp; staged
// via SMEM. Aggregation: lane loads 4 half2 per edge (slot i covers head
// 2i+(lane>>4), channels 2*(lane&15)..+1). fp32 accumulate, deferred norm.
// ===========================================================================
__global__ void __launch_bounds__(256) gat_fused8_k(const float* __restrict__ bias,
                                                    int relu, int layer)
{
    __shared__ float sex[8][32];
    __shared__ int   ssrc[8][4];

    int w = (blockIdx.x * blockDim.x + threadIdx.x) >> 5;
    int lane = threadIdx.x & 31;
    int wl = (threadIdx.x >> 5);
    if (w >= NN) return;
    int d = w;
    int beg = g_rows[d], end = g_rows[d + 1];

    int hsel  = lane & 7;    // head this lane computes exp for
    int eslot = lane >> 3;   // edge slot within chunk (0-3)
    int hi    = lane >> 4;   // aggregation head offset (0 or 1)

    float adh = __ldg(&g_adst[d * 8 + hsel]);
    float bh  = g_gmax[layer][hsel] + g_gmax[layer][8 + hsel];
    float bndh = bh > 0.f ? bh : 0.2f * bh;

    float2 acc2[4];
    #pragma unroll
    for (int i = 0; i < 4; i++) acc2[i] = make_float2(0.f, 0.f);
    float smpart = 0.f;

    int p0 = beg;
    int nfull = (end - beg) >> 2;
    for (int ch = 0; ch < nfull; ch++, p0 += 4) {
        int s = __ldg(&g_colsrc[p0 + eslot]);
        float e = __ldg(&g_asrc[s * 8 + hsel]) + adh;
        e = e > 0.f ? e : 0.2f * e;
        float ex = __expf(e - bndh);
        smpart += ex;
        sex[wl][lane] = ex;
        if (hsel == 0) ssrc[wl][eslot] = s;
        __syncwarp();
        #pragma unroll
        for (int e4 = 0; e4 < 4; e4++) {
            int se = ssrc[wl][e4];
            const __half2* hp = (const __half2*)(g_h16 + (size_t)se * F1);
            #pragma unroll
            for (int i = 0; i < 4; i++) {
                float wgt = sex[wl][e4 * 8 + 2 * i + hi];
                float2 f = __half22float2(__ldg(&hp[i * 32 + lane]));
                acc2[i].x = fmaf(wgt, f.x, acc2[i].x);
                acc2[i].y = fmaf(wgt, f.y, acc2[i].y);
            }
        }
        __syncwarp();
    }
    int rem = end - p0;
    if (rem > 0) {
        float ex = 0.f;
        int s = 0;
        if (eslot < rem) {
            s = __ldg(&g_colsrc[p0 + eslot]);
            float e = __ldg(&g_asrc[s * 8 + hsel]) + adh;
            e = e > 0.f ? e : 0.2f * e;
            ex = __expf(e - bndh);
            smpart += ex;
        }
        sex[wl][lane] = ex;
        if (hsel == 0 && eslot < rem) ssrc[wl][eslot] = s;
        __syncwarp();
        for (int e4 = 0; e4 < rem; e4++) {
            int se = ssrc[wl][e4];
            const __half2* hp = (const __half2*)(g_h16 + (size_t)se * F1);
            #pragma unroll
            for (int i = 0; i < 4; i++) {
                float wgt = sex[wl][e4 * 8 + 2 * i + hi];
                float2 f = __half22float2(__ldg(&hp[i * 32 + lane]));
                acc2[i].x = fmaf(wgt, f.x, acc2[i].x);
                acc2[i].y = fmaf(wgt, f.y, acc2[i].y);
            }
        }
        __syncwarp();
    }

    // complete per-head sums: lanes {h, h+8, h+16, h+24} hold partials of head h
    smpart += __shfl_xor_sync(0xffffffffu, smpart, 8);
    smpart += __shfl_xor_sync(0xffffffffu, smpart, 16);
    float invl = 1.f / (smpart + 1e-16f);   // lane holds inv for head (lane&7)

    float* op = g_out + (size_t)d * F1;
    int c0 = (lane & 15) * 2;
    #pragma unroll
    for (int i = 0; i < 4; i++) {
        int head = 2 * i + hi;
        float inv = __shfl_sync(0xffffffffu, invl, head);
        float v0 = acc2[i].x * inv + bias[head * 32 + c0];
        float v1 = acc2[i].y * inv + bias[head * 32 + c0 + 1];
        if (relu) { v0 = fmaxf(v0, 0.f); v1 = fmaxf(v1, 0.f); }
        *(float2*)&op[head * 32 + c0] = make_float2(v0, v1);
    }
}

// ===========================================================================
// SINGLE-PASS fused layer-3: 1 head x 40 ch + bias + log_softmax, fp16 h
// ===========================================================================
__global__ void __launch_bounds__(256) gat_fused1_k(const float* __restrict__ bias,
                                                    float* __restrict__ out, int layer)
{
    __shared__ float sex[8][32];
    __shared__ int   ssrc[8][32];

    int w = (blockIdx.x * blockDim.x + threadIdx.x) >> 5;
    int lane = threadIdx.x & 31;
    int wl = (threadIdx.x >> 5);
    if (w >= NN) return;
    int d = w;
    int beg = g_rows[d], end = g_rows[d + 1];
    float add = g_adst[d];
    float b = g_gmax[layer][0] + g_gmax[layer][8];
    float bnd = b > 0.f ? b : 0.2f * b;

    float a0 = 0.f, a1 = 0.f, smpart = 0.f;

    for (int p0 = beg; p0 < end; p0 += 32) {
        int ne = min(32, end - p0);
        float ex = 0.f;
        int s = 0;
        if (lane < ne) {
            s = __ldg(&g_colsrc[p0 + lane]);
            float e = __ldg(&g_asrc[s]) + add;
            e = e > 0.f ? e : 0.2f * e;
            ex = __expf(e - bnd);
            smpart += ex;
        }
        sex[wl][lane] = ex;
        ssrc[wl][lane] = s;
        __syncwarp();
        for (int e = 0; e < ne; e++) {
            int se = ssrc[wl][e];
            float al = sex[wl][e];
            const __half* hp = g_h16 + (size_t)se * OUTC;
            a0 = fmaf(al, __half2float(__ldg(&hp[lane])), a0);
            if (lane < 8) a1 = fmaf(al, __half2float(__ldg(&hp[lane + 32])), a1);
        }
        __syncwarp();
    }
    #pragma unroll
    for (int o = 16; o; o >>= 1) smpart += __shfl_xor_sync(0xffffffffu, smpart, o);
    float inv = 1.f / (smpart + 1e-16f);

    float v0 = a0 * inv + bias[lane];
    float v1 = (lane < 8) ? a1 * inv + bias[lane + 32] : -INFINITY;
    float m = fmaxf(v0, v1);
    #pragma unroll
    for (int o = 16; o; o >>= 1) m = fmaxf(m, __shfl_xor_sync(0xffffffffu, m, o));
    float s2 = __expf(v0 - m) + ((lane < 8) ? __expf(v1 - m) : 0.f);
    #pragma unroll
    for (int o = 16; o; o >>= 1) s2 += __shfl_xor_sync(0xffffffffu, s2, o);
    float lg = m + logf(s2);
    out[(size_t)d * OUTC + lane] = v0 - lg;
    if (lane < 8) out[(size_t)d * OUTC + lane + 32] = v1 - lg;
}

// ===========================================================================
// TF32 tensor-core GEMM with cp.async 2-stage double buffering.
// Epilogue writes g_h16 (fp16) directly.
// ===========================================================================
#define GBM 128
#define GBN 64
#define GBK 16
#define AS_STRIDE 20   // 16 + 4 pad
#define BS_STRIDE 72   // 64 + 8 pad

__device__ __forceinline__ void cp16(uint32_t dst, const void* src, int valid)
{
    asm volatile("cp.async.ca.shared.global [%0], [%1], 16, %2;\n"
                 :: "r"(dst), "l"(src), "r"(valid ? 16 : 0));
}

__device__ __forceinline__ void mma1688(float* c, const uint32_t* a, const uint32_t* b)
{
    asm volatile(
        "mma.sync.aligned.m16n8k8.row.col.f32.tf32.tf32.f32 "
        "{%0,%1,%2,%3},{%4,%5,%6,%7},{%8,%9},{%0,%1,%2,%3};"
        : "+f"(c[0]), "+f"(c[1]), "+f"(c[2]), "+f"(c[3])
        : "r"(a[0]), "r"(a[1]), "r"(a[2]), "r"(a[3]), "r"(b[0]), "r"(b[1]));
}

__global__ void __launch_bounds__(256) tf32gemm_k(const float* __restrict__ Aext,
                                                  const float* __restrict__ B,
                                                  int M, int Ncol, int K, int a_internal)
{
    const float* A = a_internal ? g_out : Aext;
    __shared__ float As[2][GBM * AS_STRIDE];
    __shared__ float Bs[2][GBK * BS_STRIDE];

    int tid  = threadIdx.x;
    int warp = tid >> 5;
    int lane = tid & 31;
    int wm = warp >> 1;
    int wn = warp & 1;
    int bm = blockIdx.y * GBM;
    int bn = blockIdx.x * GBN;
    int lr = lane >> 2;
    int lc = lane & 3;

    int ar0 = tid >> 2;
    int ac  = (tid & 3) * 4;
    int br  = tid >> 4;
    int bc  = (tid & 15) * 4;

    uint32_t as_base = (uint32_t)__cvta_generic_to_shared(&As[0][0]);
    uint32_t bs_base = (uint32_t)__cvta_generic_to_shared(&Bs[0][0]);
    const uint32_t AS_BYTES = GBM * AS_STRIDE * 4;
    const uint32_t BS_BYTES = GBK * BS_STRIDE * 4;

    int niter = K / GBK;

    {
        #pragma unroll
        for (int i = 0; i < 2; i++) {
            int r = ar0 + i * 64;
            int gr = bm + r;
            int ok = gr < M;
            const float* src = A + (size_t)(ok ? gr : 0) * K + ac;
            cp16(as_base + (r * AS_STRIDE + ac) * 4, src, ok);
        }
        {
            int gc = bn + bc;
            int ok = gc < Ncol;
            const float* src = B + (size_t)br * Ncol + (ok ? gc : 0);
            cp16(bs_base + (br * BS_STRIDE + bc) * 4, src, ok);
        }
        asm volatile("cp.async.commit_group;\n" ::);
    }

    float c[2][4][4];
    #pragma unroll
    for (int i = 0; i < 2; i++)
        #pragma unroll
        for (int j = 0; j < 4; j++)
            #pragma unroll
            for (int r = 0; r < 4; r++) c[i][j][r] = 0.f;

    int buf = 0;
    for (int it = 0; it < niter; it++) {
        int has_next = (it + 1 < niter);
        if (has_next) {
            int k0 = (it + 1) * GBK;
            uint32_t ab = as_base + (buf ^ 1) * AS_BYTES;
            uint32_t bb = bs_base + (buf ^ 1) * BS_BYTES;
            #pragma unroll
            for (int i = 0; i < 2; i++) {
                int r = ar0 + i * 64;
                int gr = bm + r;
                int ok = gr < M;
                const float* src = A + (size_t)(ok ? gr : 0) * K + k0 + ac;
                cp16(ab + (r * AS_STRIDE + ac) * 4, src, ok);
            }
            {
                int gc = bn + bc;
                int ok = gc < Ncol;
                const float* src = B + (size_t)(k0 + br) * Ncol + (ok ? gc : 0);
                cp16(bb + (br * BS_STRIDE + bc) * 4, src, ok);
            }
            asm volatile("cp.async.commit_group;\n" ::);
            asm volatile("cp.async.wait_group 1;\n" ::);
        } else {
            asm volatile("cp.async.wait_group 0;\n" ::);
        }
        __syncthreads();

        const float* Asb = As[buf];
        const float* Bsb = Bs[buf];
        #pragma unroll
        for (int kk = 0; kk < GBK; kk += 8) {
            uint32_t afrag[2][4], bfrag[4][2];
            #pragma unroll
            for (int i = 0; i < 2; i++) {
                int rb = wm * 32 + i * 16;
                afrag[i][0] = __float_as_uint(Asb[(rb + lr)     * AS_STRIDE + kk + lc]);
                afrag[i][1] = __float_as_uint(Asb[(rb + 8 + lr) * AS_STRIDE + kk + lc]);
                afrag[i][2] = __float_as_uint(Asb[(rb + lr)     * AS_STRIDE + kk + 4 + lc]);
                afrag[i][3] = __float_as_uint(Asb[(rb + 8 + lr) * AS_STRIDE + kk + 4 + lc]);
            }
            #pragma unroll
            for (int j = 0; j < 4; j++) {
                int nb = wn * 32 + j * 8;
                bfrag[j][0] = __float_as_uint(Bsb[(kk + lc)     * BS_STRIDE + nb + lr]);
                bfrag[j][1] = __float_as_uint(Bsb[(kk + 4 + lc) * BS_STRIDE + nb + lr]);
            }
            #pragma unroll
            for (int i = 0; i < 2; i++)
                #pragma unroll
                for (int j = 0; j < 4; j++)
                    mma1688(c[i][j], afrag[i], bfrag[j]);
        }
        __syncthreads();
        buf ^= 1;
    }

    // epilogue: pack adjacent-column pairs to half2, one STG.32 each
    #pragma unroll
    for (int i = 0; i < 2; i++) {
        int r0 = bm + wm * 32 + i * 16 + lr;
        #pragma unroll
        for (int j = 0; j < 4; j++) {
            int col = bn + wn * 32 + j * 8 + lc * 2;
            if (col < Ncol) {
                if (r0 < M)
                    *(__half2*)&g_h16[(size_t)r0 * Ncol + col] =
                        __floats2half2_rn(c[i][j][0], c[i][j][1]);
                if (r0 + 8 < M)
                    *(__half2*)&g_h16[(size_t)(r0 + 8) * Ncol + col] =
                        __floats2half2_rn(c[i][j][2], c[i][j][3]);
            }
        }
    }
}

// ===========================================================================
// Launcher
// ===========================================================================
extern "C" void kernel_launch(void* const* d_in, const int* in_sizes, int n_in,
                              void* d_out, int out_size)
{
    const float* x    = (const float*)d_in[0];
    const int*   ei   = (const int*)  d_in[1];
    const int*   srcv = ei;
    const int*   dstv = ei + EE;
    const float* W1  = (const float*)d_in[2];
    const float* as1 = (const float*)d_in[3];
    const float* ad1 = (const float*)d_in[4];
    const float* b1  = (const float*)d_in[5];
    const float* W2  = (const float*)d_in[6];
    const float* as2 = (const float*)d_in[7];
    const float* ad2 = (const float*)d_in[8];
    const float* b2  = (const float*)d_in[9];
    const float* W3  = (const float*)d_in[10];
    const float* as3 = (const float*)d_in[11];
    const float* ad3 = (const float*)d_in[12];
    const float* b3  = (const float*)d_in[13];
    float* out = (float*)d_out;

    dim3 blk(256);
    dim3 gemm_g1((F1 + GBN - 1) / GBN,   (NN + GBM - 1) / GBM);
    dim3 gemm_g3((OUTC + GBN - 1) / GBN, (NN + GBM - 1) / GBM);
    int nbN    = (NN + 255) / 256;
    int nbE    = (EE + 255) / 256;
    int nbE2   = (E2V + 255) / 256;
    int nbNH   = (NN * 8 + 255) / 256;
    int nbWarp = (NN * 32 + 255) / 256;

    // ---- CSR build (also resets g_gmax) ----
    init_deg_k<<<nbN, blk>>>();
    count_k<<<nbE, blk>>>(dstv);
    scan1_k<<<NBLK, SB>>>();
    scan2_k<<<1, 128>>>();
    scan3_k<<<nbN, blk>>>();
    scatter_k<<<nbE2, blk>>>(srcv, dstv);

    // ---- layer 1: 128 -> 8x32 ----
    tf32gemm_k<<<gemm_g1, blk>>>(x, W1, NN, F1, 128, 0);
    dots_k<8><<<nbNH, blk>>>(as1, ad1, 32, 0);
    gat_fused8_k<<<nbWarp, blk>>>(b1, 1, 0);

    // ---- layer 2: 256 -> 8x32 ----
    tf32gemm_k<<<gemm_g1, blk>>>(nullptr, W2, NN, F1, F1, 1);
    dots_k<8><<<nbNH, blk>>>(as2, ad2, 32, 1);
    gat_fused8_k<<<nbWarp, blk>>>(b2, 1, 1);

    // ---- layer 3: 256 -> 40 + log_softmax ----
    tf32gemm_k<<<gemm_g3, blk>>>(nullptr, W3, NN, OUTC, F1, 1);
    dots_k<1><<<nbN, blk>>>(as3, ad3, OUTC, 2);
    gat_fused1_k<<<nbWarp, blk>>>(b3, out, 2);
}